// round 14
// baseline (speedup 1.0000x reference)
#include <cuda_runtime.h>
#include <cuda_fp16.h>

#define NN 100000
#define NE 1000000
#define NG 512
#define HID 64
#define EDIM 32
#define ZW 160
#define NLAYERS 4

typedef unsigned long long ull;
typedef unsigned int uint;

// ---------------- scratch ----------------
__device__ float d_x[NN * HID];
__device__ uint  d_nd[NN * 64];       // dst terms: half2(Af), half2(As) (bias incl.)
__device__ uint  d_ns[NN * 64];       // src terms: half2(Bf), half2(Bs)
__device__ float d_agg[NN * HID];
__device__ __half d_ea_h[NE * EDIM];  // fp16 edge_attr (pre-converted once)
__device__ double d_sum1[NLAYERS][64];
__device__ double d_sumsq1[NLAYERS][64];
__device__ double d_sum2[NLAYERS][64];
__device__ double d_sumsq2[NLAYERS][64];
__device__ float d_pool[NG * HID];
__device__ float d_cnt[NG];

// ---------------- helpers ----------------
__device__ __forceinline__ float sigmoidf_(float x) {
    return __fdividef(1.0f, 1.0f + __expf(-x));
}
__device__ __forceinline__ float sigmoid_tanh_(float x) {
    float t;
    asm("tanh.approx.f32 %0, %1;" : "=f"(t) : "f"(x * 0.5f));
    return fmaf(0.5f, t, 0.5f);
}
__device__ __forceinline__ float softplusf_(float x) {
    float e = __expf(-fabsf(x));
    return fmaxf(x, 0.0f) + __logf(1.0f + e);
}
__device__ __forceinline__ uint h2u(__half2 h) { return *(uint*)&h; }

// mma.sync m16n8k16 f16 inputs, f32 accumulate
__device__ __forceinline__ void mma16816(float c[4], const uint a[4], const uint b[2]) {
    asm volatile(
        "mma.sync.aligned.m16n8k16.row.col.f32.f16.f16.f32 "
        "{%0,%1,%2,%3}, {%4,%5,%6,%7}, {%8,%9}, {%0,%1,%2,%3};"
        : "+f"(c[0]), "+f"(c[1]), "+f"(c[2]), "+f"(c[3])
        : "r"(a[0]), "r"(a[1]), "r"(a[2]), "r"(a[3]), "r"(b[0]), "r"(b[1]));
}
// ldmatrix x4 (A fragments for m16n8k16)
__device__ __forceinline__ void ldsm4(uint a[4], const __half* p) {
    uint sa = (uint)__cvta_generic_to_shared(p);
    asm volatile("ldmatrix.sync.aligned.m8n8.x4.shared.b16 {%0,%1,%2,%3}, [%4];"
                 : "=r"(a[0]), "=r"(a[1]), "=r"(a[2]), "=r"(a[3]) : "r"(sa));
}
// stmatrix x4 (C fragments -> smem, fp16)
__device__ __forceinline__ void stsm4(__half* p, uint r0, uint r1, uint r2, uint r3) {
    uint sa = (uint)__cvta_generic_to_shared(p);
    asm volatile("stmatrix.sync.aligned.m8n8.x4.shared.b16 [%0], {%1,%2,%3,%4};"
                 :: "r"(sa), "r"(r0), "r"(r1), "r"(r2), "r"(r3));
}

// ---------------- kernels ----------------

__global__ void k_gather(const int* __restrict__ z, const float* __restrict__ emb) {
    int i = blockIdx.x * blockDim.x + threadIdx.x;
    if (i < NN * HID) {
        int n = i >> 6, c = i & 63;
        d_x[i] = emb[z[n] * HID + c];
        d_agg[i] = 0.f;
    }
    if (i < NLAYERS * 64) {
        int l = i >> 6, c = i & 63;
        d_sum1[l][c] = 0.0; d_sumsq1[l][c] = 0.0;
        d_sum2[l][c] = 0.0; d_sumsq2[l][c] = 0.0;
    }
}

// one-time: convert edge_attr fp32 -> fp16
__global__ void k_prep_ea(const float* __restrict__ ea) {
    int i = blockIdx.x * blockDim.x + threadIdx.x;
    if (i < NE * EDIM / 8) {
        const float4* s = (const float4*)ea;
        float4 v0 = __ldcs(s + 2 * i);
        float4 v1 = __ldcs(s + 2 * i + 1);
        uint4 o;
        o.x = h2u(__floats2half2_rn(v0.x, v0.y));
        o.y = h2u(__floats2half2_rn(v0.z, v0.w));
        o.z = h2u(__floats2half2_rn(v1.x, v1.y));
        o.w = h2u(__floats2half2_rn(v1.z, v1.w));
        ((uint4*)d_ea_h)[i] = o;
    }
}

// Tensor-core node pre-GEMM (ldmatrix A-fragments).
__global__ __launch_bounds__(256) void k_node_pre(
    const float* __restrict__ Wf, const float* __restrict__ bf,
    const float* __restrict__ Ws, const float* __restrict__ bs,
    const float* __restrict__ go, const float* __restrict__ bo,
    int prev_layer)
{
    __shared__ __half sxh[64][72];

    int tid = threadIdx.x;
    int warp = tid >> 5;
    int lane = tid & 31;
    int gid = lane >> 2;
    int tig = lane & 3;

    float mn[4], rsg[4], bb[4];
    if (prev_layer >= 0) {
        int q = tid & 15;
#pragma unroll
        for (int j = 0; j < 4; j++) {
            int c = 4 * q + j;
            double mean = d_sum2[prev_layer][c] * (1.0 / NN);
            double var  = d_sumsq2[prev_layer][c] * (1.0 / NN) - mean * mean;
            float rs = (float)rsqrt(var + 1e-5);
            mn[j] = (float)mean; rsg[j] = rs * go[c]; bb[j] = bo[c];
        }
    }

    int m = warp >> 1;
    int chb = (warp & 1) * 32;
    const float* Wsrc;
    const float* bias = nullptr;
    uint* outp;
    int slot;
    if (m == 0)      { Wsrc = Wf;            bias = bf; outp = d_nd; slot = 0; }
    else if (m == 1) { Wsrc = Wf + 64 * HID;            outp = d_ns; slot = 0; }
    else if (m == 2) { Wsrc = Ws;            bias = bs; outp = d_nd; slot = 1; }
    else             { Wsrc = Ws + 64 * HID;            outp = d_ns; slot = 1; }

    uint b[4][4][2];
#pragma unroll
    for (int nt = 0; nt < 4; nt++) {
#pragma unroll
        for (int kt = 0; kt < 4; kt++) {
            int ch = chb + nt * 8 + gid;
            int k0 = kt * 16 + tig * 2;
            b[nt][kt][0] = h2u(__floats2half2_rn(Wsrc[k0 * HID + ch],
                                                 Wsrc[(k0 + 1) * HID + ch]));
            b[nt][kt][1] = h2u(__floats2half2_rn(Wsrc[(k0 + 8) * HID + ch],
                                                 Wsrc[(k0 + 9) * HID + ch]));
        }
    }
    float bi[4][2];
#pragma unroll
    for (int nt = 0; nt < 4; nt++) {
        int ch = chb + nt * 8 + tig * 2;
        bi[nt][0] = bias ? bias[ch]     : 0.f;
        bi[nt][1] = bias ? bias[ch + 1] : 0.f;
    }

    int lrow = lane & 15;
    int lcol = (lane >> 4) * 8;

    for (int nb = blockIdx.x * 64; nb < NN; nb += gridDim.x * 64) {
        int nmax = NN - nb; if (nmax > 64) nmax = 64;

        {
            const float4* x4 = (const float4*)(d_x + (ull)nb * HID);
            float4* a4 = (float4*)(d_agg + (ull)nb * HID);
            float4* xw4 = (float4*)(d_x + (ull)nb * HID);
            for (int i = tid; i < nmax * 16; i += 256) {
                int n = i >> 4, q = i & 15;
                float4 v;
                if (prev_layer >= 0) {
                    float4 a = a4[i];
                    v.x = softplusf_((a.x - mn[0]) * rsg[0] + bb[0]);
                    v.y = softplusf_((a.y - mn[1]) * rsg[1] + bb[1]);
                    v.z = softplusf_((a.z - mn[2]) * rsg[2] + bb[2]);
                    v.w = softplusf_((a.w - mn[3]) * rsg[3] + bb[3]);
                    xw4[i] = v;
                    a4[i] = make_float4(0.f, 0.f, 0.f, 0.f);
                } else {
                    v = x4[i];
                }
                __half2 h0 = __floats2half2_rn(v.x, v.y);
                __half2 h1 = __floats2half2_rn(v.z, v.w);
                *(uint2*)&sxh[n][4 * q] = make_uint2(h2u(h0), h2u(h1));
            }
        }
        __syncthreads();

#pragma unroll
        for (int mt = 0; mt < 4; mt++) {
            float c[4][4];
#pragma unroll
            for (int nt = 0; nt < 4; nt++) {
                c[nt][0] = bi[nt][0]; c[nt][1] = bi[nt][1];
                c[nt][2] = bi[nt][0]; c[nt][3] = bi[nt][1];
            }
#pragma unroll
            for (int kt = 0; kt < 4; kt++) {
                uint a[4];
                ldsm4(a, &sxh[mt * 16 + lrow][kt * 16 + lcol]);
#pragma unroll
                for (int nt = 0; nt < 4; nt++)
                    mma16816(c[nt], a, b[nt][kt]);
            }
            int r0 = nb + mt * 16 + gid;
            int r1 = r0 + 8;
#pragma unroll
            for (int nt = 0; nt < 4; nt++) {
                int ch = chb + nt * 8 + tig * 2;
                if (r0 < NN) outp[(ull)r0 * 64 + ch + slot] = h2u(__floats2half2_rn(c[nt][0], c[nt][1]));
                if (r1 < NN) outp[(ull)r1 * 64 + ch + slot] = h2u(__floats2half2_rn(c[nt][2], c[nt][3]));
            }
        }
        __syncthreads();
    }
}

__global__ void k_zero_pool() {
    int i = blockIdx.x * blockDim.x + threadIdx.x;
    if (i < NG * HID) d_pool[i] = 0.f;
    if (i < NG) d_cnt[i] = 0.f;
}

// Fused edge kernel: HMMA GEMM (ldmatrix A, stmatrix C) + fp16 sE + apply.
__global__ __launch_bounds__(128, 6) void k_edge_fused(
    const int* __restrict__ ei,
    const float* __restrict__ Wf, const float* __restrict__ Ws)
{
    __shared__ __half sea_h[32][40];
    __shared__ uint sE[32][68];       // fp16 GEMM result: [e][col] half2 cols; f=0-31, s=32-63
    __shared__ int sidx[64];

    int tid = threadIdx.x;
    int warp = tid >> 5;
    int lane = tid & 31;
    int gid = lane >> 2;
    int tig = lane & 3;

    const float* W = (warp >> 1) ? Ws : Wf;
    int chb = (warp & 1) * 32;
    int outb2 = (warp >> 1) * 32 + (warp & 1) * 16;   // half2-col base

    uint b[4][2][2];
#pragma unroll
    for (int nt = 0; nt < 4; nt++) {
#pragma unroll
        for (int kt = 0; kt < 2; kt++) {
            int ch = chb + nt * 8 + gid;
            int k0 = kt * 16 + tig * 2;
            b[nt][kt][0] = h2u(__floats2half2_rn(W[(128 + k0)     * HID + ch],
                                                 W[(128 + k0 + 1) * HID + ch]));
            b[nt][kt][1] = h2u(__floats2half2_rn(W[(128 + k0 + 8) * HID + ch],
                                                 W[(128 + k0 + 9) * HID + ch]));
        }
    }

    int lrow = lane & 15;
    int lcol = (lane >> 4) * 8;
    // stmatrix target for this lane: mats {ntX-lo, ntX-hi, ntY-lo, ntY-hi}
    int srow_off = ((lane >> 3) & 1) * 8 + (lane & 7);
    int scol_off = outb2 + ((lane >> 4) << 2);

    const int stride = gridDim.x * 32;
    int base = blockIdx.x * 32;

    if (base < NE) {
        if (tid < 32)      sidx[tid] = ei[base + tid];
        else if (tid < 64) sidx[tid] = ei[NE + base + tid - 32];
        uint4 t = __ldcs(((const uint4*)(d_ea_h + (ull)base * EDIM)) + tid);
        int e = tid >> 2, seg = tid & 3;
        *(uint4*)&sea_h[e][seg * 8] = t;
    }
    __syncthreads();

    for (; base < NE; base += stride) {
        int nb = base + stride;
        int lb = (nb < NE) ? nb : 0;

        int srcs[8], dsts[8];
#pragma unroll
        for (int t = 0; t < 8; t++) {
            srcs[t] = sidx[warp * 8 + t];
            dsts[t] = sidx[32 + warp * 8 + t];
        }

        uint4 nv = __ldcs(((const uint4*)(d_ea_h + (ull)lb * EDIM)) + tid);
        int nidx = 0;
        if (tid < 32)      nidx = ei[lb + tid];
        else if (tid < 64) nidx = ei[NE + lb + tid - 32];

        // ---- GEMM: sequential m-tiles, ldmatrix A, stmatrix C ----
#pragma unroll
        for (int mt = 0; mt < 2; mt++) {
            float c[4][4];
#pragma unroll
            for (int nt = 0; nt < 4; nt++)
#pragma unroll
                for (int j = 0; j < 4; j++) c[nt][j] = 0.f;
#pragma unroll
            for (int kt = 0; kt < 2; kt++) {
                uint a[4];
                ldsm4(a, &sea_h[mt * 16 + lrow][kt * 16 + lcol]);
#pragma unroll
                for (int nt = 0; nt < 4; nt++)
                    mma16816(c[nt], a, b[nt][kt]);
            }
            __half* p0 = (__half*)&sE[mt * 16 + srow_off][scol_off];
            stsm4(p0,
                  h2u(__floats2half2_rn(c[0][0], c[0][1])),
                  h2u(__floats2half2_rn(c[0][2], c[0][3])),
                  h2u(__floats2half2_rn(c[1][0], c[1][1])),
                  h2u(__floats2half2_rn(c[1][2], c[1][3])));
            stsm4(p0 + 16,   // +8 uint cols = nt2/nt3 block
                  h2u(__floats2half2_rn(c[2][0], c[2][1])),
                  h2u(__floats2half2_rn(c[2][2], c[2][3])),
                  h2u(__floats2half2_rn(c[3][0], c[3][1])),
                  h2u(__floats2half2_rn(c[3][2], c[3][3])));
        }
        __syncthreads();   // sE ready; sea_h/sidx free

        {
            int e = tid >> 2, seg = tid & 3;
            *(uint4*)&sea_h[e][seg * 8] = nv;
            if (tid < 64) sidx[tid] = nidx;
        }

        // ---- apply: two batches of 4 edges ----
#pragma unroll
        for (int g2 = 0; g2 < 2; g2++) {
            uint2 nd[4], ns[4];
#pragma unroll
            for (int t = 0; t < 4; t++) {
                int idx = g2 * 4 + t;
                nd[t] = __ldg((const uint2*)&d_nd[(ull)dsts[idx] * 64 + 2 * lane]);
                ns[t] = __ldg((const uint2*)&d_ns[(ull)srcs[idx] * 64 + 2 * lane]);
            }
#pragma unroll
            for (int t = 0; t < 4; t++) {
                int idx = g2 * 4 + t;
                int e = warp * 8 + idx;
                float2 afv = __half22float2(*(__half2*)&nd[t].x);
                float2 asv = __half22float2(*(__half2*)&nd[t].y);
                float2 bfv = __half22float2(*(__half2*)&ns[t].x);
                float2 bsv = __half22float2(*(__half2*)&ns[t].y);

                float2 Ef = __half22float2(*(__half2*)&sE[e][lane]);
                float2 Es = __half22float2(*(__half2*)&sE[e][32 + lane]);

                float pf0 = Ef.x + afv.x + bfv.x;
                float pf1 = Ef.y + afv.y + bfv.y;
                float ps0 = Es.x + asv.x + bsv.x;
                float ps1 = Es.y + asv.y + bsv.y;

                float m0 = sigmoid_tanh_(pf0) * softplusf_(ps0);
                float m1 = sigmoid_tanh_(pf1) * softplusf_(ps1);

                float* dp = d_agg + (ull)dsts[idx] * HID + 2 * lane;
                asm volatile("red.global.add.v2.f32 [%0], {%1,%2};"
                             :: "l"(dp), "f"(m0), "f"(m1) : "memory");
            }
        }
        __syncthreads();
    }
}

// float4-vectorized channel stats of d_agg -> d_sum1[layer]
__global__ void k_stats_agg(int layer) {
    int tid = threadIdx.x;
    float4 s = {0,0,0,0}, q = {0,0,0,0};
    int stride = gridDim.x * blockDim.x;
    const float4* a4 = (const float4*)d_agg;
    for (int i = blockIdx.x * blockDim.x + tid; i < NN * 16; i += stride) {
        float4 v = a4[i];
        s.x += v.x; s.y += v.y; s.z += v.z; s.w += v.w;
        q.x = fmaf(v.x, v.x, q.x); q.y = fmaf(v.y, v.y, q.y);
        q.z = fmaf(v.z, v.z, q.z); q.w = fmaf(v.w, v.w, q.w);
    }
    __shared__ float4 ss[256], sq[256];
    ss[tid] = s; sq[tid] = q;
    __syncthreads();
#pragma unroll
    for (int o = 128; o >= 16; o >>= 1) {
        if (tid < o) {
            ss[tid].x += ss[tid+o].x; ss[tid].y += ss[tid+o].y;
            ss[tid].z += ss[tid+o].z; ss[tid].w += ss[tid+o].w;
            sq[tid].x += sq[tid+o].x; sq[tid].y += sq[tid+o].y;
            sq[tid].z += sq[tid+o].z; sq[tid].w += sq[tid+o].w;
        }
        __syncthreads();
    }
    if (tid < 16) {
        atomicAdd(&d_sum1[layer][4*tid+0], (double)ss[tid].x);
        atomicAdd(&d_sum1[layer][4*tid+1], (double)ss[tid].y);
        atomicAdd(&d_sum1[layer][4*tid+2], (double)ss[tid].z);
        atomicAdd(&d_sum1[layer][4*tid+3], (double)ss[tid].w);
        atomicAdd(&d_sumsq1[layer][4*tid+0], (double)sq[tid].x);
        atomicAdd(&d_sumsq1[layer][4*tid+1], (double)sq[tid].y);
        atomicAdd(&d_sumsq1[layer][4*tid+2], (double)sq[tid].z);
        atomicAdd(&d_sumsq1[layer][4*tid+3], (double)sq[tid].w);
    }
}

// apply cbn + residual (float4), write x_new into d_agg, accumulate obn stats
__global__ void k_apply_cbn(const float* __restrict__ gc, const float* __restrict__ bc, int layer) {
    int tid = threadIdx.x;
    int g = tid & 15;
    float mn[4], rsg[4], bb[4];
#pragma unroll
    for (int j = 0; j < 4; j++) {
        int c = 4 * g + j;
        double mean = d_sum1[layer][c] * (1.0 / NN);
        double var  = d_sumsq1[layer][c] * (1.0 / NN) - mean * mean;
        float rs = (float)rsqrt(var + 1e-5);
        mn[j] = (float)mean; rsg[j] = rs * gc[c]; bb[j] = bc[c];
    }
    float4 s = {0,0,0,0}, q = {0,0,0,0};
    int stride = gridDim.x * blockDim.x;
    float4* a4 = (float4*)d_agg;
    const float4* x4 = (const float4*)d_x;
    for (int i = blockIdx.x * blockDim.x + tid; i < NN * 16; i += stride) {
        float4 a = a4[i];
        float4 x = x4[i];
        float4 xn;
        xn.x = (a.x - mn[0]) * rsg[0] + bb[0] + x.x;
        xn.y = (a.y - mn[1]) * rsg[1] + bb[1] + x.y;
        xn.z = (a.z - mn[2]) * rsg[2] + bb[2] + x.z;
        xn.w = (a.w - mn[3]) * rsg[3] + bb[3] + x.w;
        a4[i] = xn;
        s.x += xn.x; s.y += xn.y; s.z += xn.z; s.w += xn.w;
        q.x = fmaf(xn.x, xn.x, q.x); q.y = fmaf(xn.y, xn.y, q.y);
        q.z = fmaf(xn.z, xn.z, q.z); q.w = fmaf(xn.w, xn.w, q.w);
    }
    __shared__ float4 ss[256], sq[256];
    ss[tid] = s; sq[tid] = q;
    __syncthreads();
#pragma unroll
    for (int o = 128; o >= 16; o >>= 1) {
        if (tid < o) {
            ss[tid].x += ss[tid+o].x; ss[tid].y += ss[tid+o].y;
            ss[tid].z += ss[tid+o].z; ss[tid].w += ss[tid+o].w;
            sq[tid].x += sq[tid+o].x; sq[tid].y += sq[tid+o].y;
            sq[tid].z += sq[tid+o].z; sq[tid].w += sq[tid+o].w;
        }
        __syncthreads();
    }
    if (tid < 16) {
        atomicAdd(&d_sum2[layer][4*tid+0], (double)ss[tid].x);
        atomicAdd(&d_sum2[layer][4*tid+1], (double)ss[tid].y);
        atomicAdd(&d_sum2[layer][4*tid+2], (double)ss[tid].z);
        atomicAdd(&d_sum2[layer][4*tid+3], (double)ss[tid].w);
        atomicAdd(&d_sumsq2[layer][4*tid+0], (double)sq[tid].x);
        atomicAdd(&d_sumsq2[layer][4*tid+1], (double)sq[tid].y);
        atomicAdd(&d_sumsq2[layer][4*tid+2], (double)sq[tid].z);
        atomicAdd(&d_sumsq2[layer][4*tid+3], (double)sq[tid].w);
    }
}

// final obn + softplus -> d_x (last layer only)
__global__ void k_final_obn(const float* __restrict__ go, const float* __restrict__ bo, int layer) {
    int tid = threadIdx.x;
    int g = tid & 15;
    float mn[4], rsg[4], bb[4];
#pragma unroll
    for (int j = 0; j < 4; j++) {
        int c = 4 * g + j;
        double mean = d_sum2[layer][c] * (1.0 / NN);
        double var  = d_sumsq2[layer][c] * (1.0 / NN) - mean * mean;
        float rs = (float)rsqrt(var + 1e-5);
        mn[j] = (float)mean; rsg[j] = rs * go[c]; bb[j] = bo[c];
    }
    int stride = gridDim.x * blockDim.x;
    const float4* a4 = (const float4*)d_agg;
    float4* x4 = (float4*)d_x;
    for (int i = blockIdx.x * blockDim.x + tid; i < NN * 16; i += stride) {
        float4 a = a4[i];
        float4 r;
        r.x = softplusf_((a.x - mn[0]) * rsg[0] + bb[0]);
        r.y = softplusf_((a.y - mn[1]) * rsg[1] + bb[1]);
        r.z = softplusf_((a.z - mn[2]) * rsg[2] + bb[2]);
        r.w = softplusf_((a.w - mn[3]) * rsg[3] + bb[3]);
        x4[i] = r;
    }
}

__global__ void k_pool(const int* __restrict__ batch) {
    int i = blockIdx.x * blockDim.x + threadIdx.x;
    if (i < NN * 16) {
        int n = i >> 4, q = i & 15;
        int g = batch[n];
        float4 v = *(const float4*)(d_x + n * HID + 4 * q);
        float* p = d_pool + g * HID + 4 * q;
        asm volatile("red.global.add.v4.f32 [%0], {%1,%2,%3,%4};"
                     :: "l"(p), "f"(v.x), "f"(v.y), "f"(v.z), "f"(v.w) : "memory");
    }
}

__global__ void k_cnt(const int* __restrict__ batch) {
    int n = blockIdx.x * blockDim.x + threadIdx.x;
    if (n < NN) atomicAdd(&d_cnt[batch[n]], 1.0f);
}

__global__ void k_head(const float* __restrict__ W1, const float* __restrict__ b1,
                       const float* __restrict__ W2, const float* __restrict__ b2,
                       float* __restrict__ out)
{
    int g = blockIdx.x;
    int t = threadIdx.x;
    __shared__ float sp[64];
    __shared__ float sh[64];
    float cnt = fmaxf(d_cnt[g], 1.0f);
    sp[t] = d_pool[g * HID + t] / cnt;
    __syncthreads();
    float acc = b1[t];
#pragma unroll
    for (int k = 0; k < 64; k++)
        acc = fmaf(sp[k], W1[k * HID + t], acc);
    float h = acc * sigmoidf_(acc);
    sh[t] = h * W2[t];
    __syncthreads();
    if (t < 32) {
        float v = sh[t] + sh[t + 32];
#pragma unroll
        for (int o = 16; o > 0; o >>= 1)
            v += __shfl_down_sync(0xffffffffu, v, o);
        if (t == 0) out[g] = v + b2[0];
    }
}

// ---------------- launch ----------------
extern "C" void kernel_launch(void* const* d_in, const int* in_sizes, int n_in,
                              void* d_out, int out_size) {
    const int*   z     = (const int*)  d_in[0];
    const int*   ei    = (const int*)  d_in[1];
    const float* ea    = (const float*)d_in[2];
    const int*   batch = (const int*)  d_in[3];
    const float* emb   = (const float*)d_in[4];
    const float* Wf    = (const float*)d_in[5];
    const float* bf    = (const float*)d_in[6];
    const float* Ws    = (const float*)d_in[7];
    const float* bs    = (const float*)d_in[8];
    const float* gc    = (const float*)d_in[9];
    const float* bc    = (const float*)d_in[10];
    const float* go    = (const float*)d_in[11];
    const float* bo    = (const float*)d_in[12];
    const float* W1    = (const float*)d_in[13];
    const float* b1    = (const float*)d_in[14];
    const float* W2    = (const float*)d_in[15];
    const float* b2    = (const float*)d_in[16];
    float* out = (float*)d_out;

    k_gather<<<(NN * HID + 255) / 256, 256>>>(z, emb);
    k_prep_ea<<<(NE * EDIM / 8 + 255) / 256, 256>>>(ea);

    for (int l = 0; l < NLAYERS; l++) {
        const float* Wfl = Wf + l * ZW * HID;
        const float* Wsl = Ws + l * ZW * HID;
        k_node_pre<<<592, 256>>>(Wfl, bf + l * HID, Wsl, bs + l * HID,
                                 go + (l - 1) * HID, bo + (l - 1) * HID, l - 1);
        k_edge_fused<<<888, 128>>>(ei, Wfl, Wsl);
        k_stats_agg<<<256, 256>>>(l);
        k_apply_cbn<<<256, 256>>>(gc + l * HID, bc + l * HID, l);
    }
    k_final_obn<<<256, 256>>>(go + 3 * HID, bo + 3 * HID, 3);

    k_zero_pool<<<(NG * HID + 255) / 256, 256>>>();
    k_pool<<<(NN * 16 + 255) / 256, 256>>>(batch);
    k_cnt<<<(NN + 255) / 256, 256>>>(batch);
    k_head<<<NG, 64>>>(W1, b1, W2, b2, out);
}

// round 15
// speedup vs baseline: 1.0377x; 1.0377x over previous
#include <cuda_runtime.h>
#include <cuda_fp16.h>

#define NN 100000
#define NE 1000000
#define NG 512
#define HID 64
#define EDIM 32
#define ZW 160
#define NLAYERS 4

typedef unsigned long long ull;
typedef unsigned int uint;

// ---------------- scratch ----------------
__device__ float d_x[NN * HID];
__device__ uint  d_nd[NN * 64];       // dst terms: half2(Af), half2(As) (bias incl.)
__device__ uint  d_ns[NN * 64];       // src terms: half2(Bf), half2(Bs)
__device__ float d_agg[NN * HID];
__device__ __half d_ea_h[NE * EDIM];  // fp16 edge_attr (pre-converted once)
__device__ double d_sum1[NLAYERS][64];
__device__ double d_sumsq1[NLAYERS][64];
__device__ double d_sum2[NLAYERS][64];
__device__ double d_sumsq2[NLAYERS][64];
__device__ float d_pool[NG * HID];
__device__ float d_cnt[NG];

// ---------------- helpers ----------------
__device__ __forceinline__ float sigmoidf_(float x) {
    return __fdividef(1.0f, 1.0f + __expf(-x));
}
__device__ __forceinline__ float sigmoid_tanh_(float x) {
    float t;
    asm("tanh.approx.f32 %0, %1;" : "=f"(t) : "f"(x * 0.5f));
    return fmaf(0.5f, t, 0.5f);
}
__device__ __forceinline__ float softplusf_(float x) {
    float e = __expf(-fabsf(x));
    return fmaxf(x, 0.0f) + __logf(1.0f + e);
}
__device__ __forceinline__ uint h2u(__half2 h) { return *(uint*)&h; }

// mma.sync m16n8k16 f16 inputs, f32 accumulate
__device__ __forceinline__ void mma16816(float c[4], const uint a[4], const uint b[2]) {
    asm volatile(
        "mma.sync.aligned.m16n8k16.row.col.f32.f16.f16.f32 "
        "{%0,%1,%2,%3}, {%4,%5,%6,%7}, {%8,%9}, {%0,%1,%2,%3};"
        : "+f"(c[0]), "+f"(c[1]), "+f"(c[2]), "+f"(c[3])
        : "r"(a[0]), "r"(a[1]), "r"(a[2]), "r"(a[3]), "r"(b[0]), "r"(b[1]));
}
// ldmatrix x4 (A fragments for m16n8k16)
__device__ __forceinline__ void ldsm4(uint a[4], const __half* p) {
    uint sa = (uint)__cvta_generic_to_shared(p);
    asm volatile("ldmatrix.sync.aligned.m8n8.x4.shared.b16 {%0,%1,%2,%3}, [%4];"
                 : "=r"(a[0]), "=r"(a[1]), "=r"(a[2]), "=r"(a[3]) : "r"(sa));
}
// stmatrix x4 (C fragments -> smem, fp16)
__device__ __forceinline__ void stsm4(__half* p, uint r0, uint r1, uint r2, uint r3) {
    uint sa = (uint)__cvta_generic_to_shared(p);
    asm volatile("stmatrix.sync.aligned.m8n8.x4.shared.b16 [%0], {%1,%2,%3,%4};"
                 :: "r"(sa), "r"(r0), "r"(r1), "r"(r2), "r"(r3));
}

// ---------------- kernels ----------------

__global__ void k_gather(const int* __restrict__ z, const float* __restrict__ emb) {
    int i = blockIdx.x * blockDim.x + threadIdx.x;
    if (i < NN * HID) {
        int n = i >> 6, c = i & 63;
        d_x[i] = emb[z[n] * HID + c];
        d_agg[i] = 0.f;
    }
    if (i < NLAYERS * 64) {
        int l = i >> 6, c = i & 63;
        d_sum1[l][c] = 0.0; d_sumsq1[l][c] = 0.0;
        d_sum2[l][c] = 0.0; d_sumsq2[l][c] = 0.0;
    }
}

// one-time: convert edge_attr fp32 -> fp16
__global__ void k_prep_ea(const float* __restrict__ ea) {
    int i = blockIdx.x * blockDim.x + threadIdx.x;
    if (i < NE * EDIM / 8) {
        const float4* s = (const float4*)ea;
        float4 v0 = __ldcs(s + 2 * i);
        float4 v1 = __ldcs(s + 2 * i + 1);
        uint4 o;
        o.x = h2u(__floats2half2_rn(v0.x, v0.y));
        o.y = h2u(__floats2half2_rn(v0.z, v0.w));
        o.z = h2u(__floats2half2_rn(v1.x, v1.y));
        o.w = h2u(__floats2half2_rn(v1.z, v1.w));
        ((uint4*)d_ea_h)[i] = o;
    }
}

// Tensor-core node pre-GEMM (ldmatrix A-fragments).
__global__ __launch_bounds__(256) void k_node_pre(
    const float* __restrict__ Wf, const float* __restrict__ bf,
    const float* __restrict__ Ws, const float* __restrict__ bs,
    const float* __restrict__ go, const float* __restrict__ bo,
    int prev_layer)
{
    __shared__ __half sxh[64][72];

    int tid = threadIdx.x;
    int warp = tid >> 5;
    int lane = tid & 31;
    int gid = lane >> 2;
    int tig = lane & 3;

    float mn[4], rsg[4], bb[4];
    if (prev_layer >= 0) {
        int q = tid & 15;
#pragma unroll
        for (int j = 0; j < 4; j++) {
            int c = 4 * q + j;
            double mean = d_sum2[prev_layer][c] * (1.0 / NN);
            double var  = d_sumsq2[prev_layer][c] * (1.0 / NN) - mean * mean;
            float rs = (float)rsqrt(var + 1e-5);
            mn[j] = (float)mean; rsg[j] = rs * go[c]; bb[j] = bo[c];
        }
    }

    int m = warp >> 1;
    int chb = (warp & 1) * 32;
    const float* Wsrc;
    const float* bias = nullptr;
    uint* outp;
    int slot;
    if (m == 0)      { Wsrc = Wf;            bias = bf; outp = d_nd; slot = 0; }
    else if (m == 1) { Wsrc = Wf + 64 * HID;            outp = d_ns; slot = 0; }
    else if (m == 2) { Wsrc = Ws;            bias = bs; outp = d_nd; slot = 1; }
    else             { Wsrc = Ws + 64 * HID;            outp = d_ns; slot = 1; }

    uint b[4][4][2];
#pragma unroll
    for (int nt = 0; nt < 4; nt++) {
#pragma unroll
        for (int kt = 0; kt < 4; kt++) {
            int ch = chb + nt * 8 + gid;
            int k0 = kt * 16 + tig * 2;
            b[nt][kt][0] = h2u(__floats2half2_rn(Wsrc[k0 * HID + ch],
                                                 Wsrc[(k0 + 1) * HID + ch]));
            b[nt][kt][1] = h2u(__floats2half2_rn(Wsrc[(k0 + 8) * HID + ch],
                                                 Wsrc[(k0 + 9) * HID + ch]));
        }
    }
    float bi[4][2];
#pragma unroll
    for (int nt = 0; nt < 4; nt++) {
        int ch = chb + nt * 8 + tig * 2;
        bi[nt][0] = bias ? bias[ch]     : 0.f;
        bi[nt][1] = bias ? bias[ch + 1] : 0.f;
    }

    int lrow = lane & 15;
    int lcol = (lane >> 4) * 8;

    for (int nb = blockIdx.x * 64; nb < NN; nb += gridDim.x * 64) {
        int nmax = NN - nb; if (nmax > 64) nmax = 64;

        {
            const float4* x4 = (const float4*)(d_x + (ull)nb * HID);
            float4* a4 = (float4*)(d_agg + (ull)nb * HID);
            float4* xw4 = (float4*)(d_x + (ull)nb * HID);
            for (int i = tid; i < nmax * 16; i += 256) {
                int n = i >> 4, q = i & 15;
                float4 v;
                if (prev_layer >= 0) {
                    float4 a = a4[i];
                    v.x = softplusf_((a.x - mn[0]) * rsg[0] + bb[0]);
                    v.y = softplusf_((a.y - mn[1]) * rsg[1] + bb[1]);
                    v.z = softplusf_((a.z - mn[2]) * rsg[2] + bb[2]);
                    v.w = softplusf_((a.w - mn[3]) * rsg[3] + bb[3]);
                    xw4[i] = v;
                    a4[i] = make_float4(0.f, 0.f, 0.f, 0.f);
                } else {
                    v = x4[i];
                }
                __half2 h0 = __floats2half2_rn(v.x, v.y);
                __half2 h1 = __floats2half2_rn(v.z, v.w);
                *(uint2*)&sxh[n][4 * q] = make_uint2(h2u(h0), h2u(h1));
            }
        }
        __syncthreads();

#pragma unroll
        for (int mt = 0; mt < 4; mt++) {
            float c[4][4];
#pragma unroll
            for (int nt = 0; nt < 4; nt++) {
                c[nt][0] = bi[nt][0]; c[nt][1] = bi[nt][1];
                c[nt][2] = bi[nt][0]; c[nt][3] = bi[nt][1];
            }
#pragma unroll
            for (int kt = 0; kt < 4; kt++) {
                uint a[4];
                ldsm4(a, &sxh[mt * 16 + lrow][kt * 16 + lcol]);
#pragma unroll
                for (int nt = 0; nt < 4; nt++)
                    mma16816(c[nt], a, b[nt][kt]);
            }
            int r0 = nb + mt * 16 + gid;
            int r1 = r0 + 8;
#pragma unroll
            for (int nt = 0; nt < 4; nt++) {
                int ch = chb + nt * 8 + tig * 2;
                if (r0 < NN) outp[(ull)r0 * 64 + ch + slot] = h2u(__floats2half2_rn(c[nt][0], c[nt][1]));
                if (r1 < NN) outp[(ull)r1 * 64 + ch + slot] = h2u(__floats2half2_rn(c[nt][2], c[nt][3]));
            }
        }
        __syncthreads();
    }
}

__global__ void k_zero_pool() {
    int i = blockIdx.x * blockDim.x + threadIdx.x;
    if (i < NG * HID) d_pool[i] = 0.f;
    if (i < NG) d_cnt[i] = 0.f;
}

// Fused edge kernel: HMMA GEMM (ldmatrix A, stmatrix C) + fp16 sE + half2 apply.
__global__ __launch_bounds__(128, 6) void k_edge_fused(
    const int* __restrict__ ei,
    const float* __restrict__ Wf, const float* __restrict__ Ws)
{
    __shared__ __half sea_h[32][40];
    __shared__ uint sE[32][68];       // fp16 GEMM result: half2 cols; f=0-31, s=32-63
    __shared__ int sidx[64];

    int tid = threadIdx.x;
    int warp = tid >> 5;
    int lane = tid & 31;
    int gid = lane >> 2;
    int tig = lane & 3;

    const float* W = (warp >> 1) ? Ws : Wf;
    int chb = (warp & 1) * 32;
    int outb2 = (warp >> 1) * 32 + (warp & 1) * 16;   // half2-col base

    uint b[4][2][2];
#pragma unroll
    for (int nt = 0; nt < 4; nt++) {
#pragma unroll
        for (int kt = 0; kt < 2; kt++) {
            int ch = chb + nt * 8 + gid;
            int k0 = kt * 16 + tig * 2;
            b[nt][kt][0] = h2u(__floats2half2_rn(W[(128 + k0)     * HID + ch],
                                                 W[(128 + k0 + 1) * HID + ch]));
            b[nt][kt][1] = h2u(__floats2half2_rn(W[(128 + k0 + 8) * HID + ch],
                                                 W[(128 + k0 + 9) * HID + ch]));
        }
    }

    int lrow = lane & 15;
    int lcol = (lane >> 4) * 8;
    int srow_off = ((lane >> 3) & 1) * 8 + (lane & 7);
    int scol_off = outb2 + ((lane >> 4) << 2);

    const int stride = gridDim.x * 32;
    int base = blockIdx.x * 32;

    if (base < NE) {
        if (tid < 32)      sidx[tid] = ei[base + tid];
        else if (tid < 64) sidx[tid] = ei[NE + base + tid - 32];
        uint4 t = __ldcs(((const uint4*)(d_ea_h + (ull)base * EDIM)) + tid);
        int e = tid >> 2, seg = tid & 3;
        *(uint4*)&sea_h[e][seg * 8] = t;
    }
    __syncthreads();

    for (; base < NE; base += stride) {
        int nb = base + stride;
        int lb = (nb < NE) ? nb : 0;

        int srcs[8], dsts[8];
#pragma unroll
        for (int t = 0; t < 8; t++) {
            srcs[t] = sidx[warp * 8 + t];
            dsts[t] = sidx[32 + warp * 8 + t];
        }

        uint4 nv = __ldcs(((const uint4*)(d_ea_h + (ull)lb * EDIM)) + tid);
        int nidx = 0;
        if (tid < 32)      nidx = ei[lb + tid];
        else if (tid < 64) nidx = ei[NE + lb + tid - 32];

        // ---- GEMM: sequential m-tiles, ldmatrix A, stmatrix C ----
#pragma unroll
        for (int mt = 0; mt < 2; mt++) {
            float c[4][4];
#pragma unroll
            for (int nt = 0; nt < 4; nt++)
#pragma unroll
                for (int j = 0; j < 4; j++) c[nt][j] = 0.f;
#pragma unroll
            for (int kt = 0; kt < 2; kt++) {
                uint a[4];
                ldsm4(a, &sea_h[mt * 16 + lrow][kt * 16 + lcol]);
#pragma unroll
                for (int nt = 0; nt < 4; nt++)
                    mma16816(c[nt], a, b[nt][kt]);
            }
            __half* p0 = (__half*)&sE[mt * 16 + srow_off][scol_off];
            stsm4(p0,
                  h2u(__floats2half2_rn(c[0][0], c[0][1])),
                  h2u(__floats2half2_rn(c[0][2], c[0][3])),
                  h2u(__floats2half2_rn(c[1][0], c[1][1])),
                  h2u(__floats2half2_rn(c[1][2], c[1][3])));
            stsm4(p0 + 16,
                  h2u(__floats2half2_rn(c[2][0], c[2][1])),
                  h2u(__floats2half2_rn(c[2][2], c[2][3])),
                  h2u(__floats2half2_rn(c[3][0], c[3][1])),
                  h2u(__floats2half2_rn(c[3][2], c[3][3])));
        }
        __syncthreads();   // sE ready; sea_h/sidx free

        {
            int e = tid >> 2, seg = tid & 3;
            *(uint4*)&sea_h[e][seg * 8] = nv;
            if (tid < 64) sidx[tid] = nidx;
        }

        // ---- apply: two batches of 4 edges; sums in fp16 (HADD2) ----
#pragma unroll
        for (int g2 = 0; g2 < 2; g2++) {
            uint2 nd[4], ns[4];
#pragma unroll
            for (int t = 0; t < 4; t++) {
                int idx = g2 * 4 + t;
                nd[t] = __ldg((const uint2*)&d_nd[(ull)dsts[idx] * 64 + 2 * lane]);
                ns[t] = __ldg((const uint2*)&d_ns[(ull)srcs[idx] * 64 + 2 * lane]);
            }
#pragma unroll
            for (int t = 0; t < 4; t++) {
                int idx = g2 * 4 + t;
                int e = warp * 8 + idx;

                __half2 Ef2 = *(__half2*)&sE[e][lane];
                __half2 Es2 = *(__half2*)&sE[e][32 + lane];
                __half2 f2 = __hadd2(__hadd2(Ef2, *(__half2*)&nd[t].x), *(__half2*)&ns[t].x);
                __half2 s2 = __hadd2(__hadd2(Es2, *(__half2*)&nd[t].y), *(__half2*)&ns[t].y);
                float2 pf = __half22float2(f2);
                float2 ps = __half22float2(s2);

                float m0 = sigmoid_tanh_(pf.x) * softplusf_(ps.x);
                float m1 = sigmoid_tanh_(pf.y) * softplusf_(ps.y);

                float* dp = d_agg + (ull)dsts[idx] * HID + 2 * lane;
                asm volatile("red.global.add.v2.f32 [%0], {%1,%2};"
                             :: "l"(dp), "f"(m0), "f"(m1) : "memory");
            }
        }
        __syncthreads();
    }
}

// float4-vectorized channel stats of d_agg -> d_sum1[layer]
__global__ void k_stats_agg(int layer) {
    int tid = threadIdx.x;
    float4 s = {0,0,0,0}, q = {0,0,0,0};
    int stride = gridDim.x * blockDim.x;
    const float4* a4 = (const float4*)d_agg;
    for (int i = blockIdx.x * blockDim.x + tid; i < NN * 16; i += stride) {
        float4 v = a4[i];
        s.x += v.x; s.y += v.y; s.z += v.z; s.w += v.w;
        q.x = fmaf(v.x, v.x, q.x); q.y = fmaf(v.y, v.y, q.y);
        q.z = fmaf(v.z, v.z, q.z); q.w = fmaf(v.w, v.w, q.w);
    }
    __shared__ float4 ss[256], sq[256];
    ss[tid] = s; sq[tid] = q;
    __syncthreads();
#pragma unroll
    for (int o = 128; o >= 16; o >>= 1) {
        if (tid < o) {
            ss[tid].x += ss[tid+o].x; ss[tid].y += ss[tid+o].y;
            ss[tid].z += ss[tid+o].z; ss[tid].w += ss[tid+o].w;
            sq[tid].x += sq[tid+o].x; sq[tid].y += sq[tid+o].y;
            sq[tid].z += sq[tid+o].z; sq[tid].w += sq[tid+o].w;
        }
        __syncthreads();
    }
    if (tid < 16) {
        atomicAdd(&d_sum1[layer][4*tid+0], (double)ss[tid].x);
        atomicAdd(&d_sum1[layer][4*tid+1], (double)ss[tid].y);
        atomicAdd(&d_sum1[layer][4*tid+2], (double)ss[tid].z);
        atomicAdd(&d_sum1[layer][4*tid+3], (double)ss[tid].w);
        atomicAdd(&d_sumsq1[layer][4*tid+0], (double)sq[tid].x);
        atomicAdd(&d_sumsq1[layer][4*tid+1], (double)sq[tid].y);
        atomicAdd(&d_sumsq1[layer][4*tid+2], (double)sq[tid].z);
        atomicAdd(&d_sumsq1[layer][4*tid+3], (double)sq[tid].w);
    }
}

// apply cbn + residual (float4), write x_new into d_agg, accumulate obn stats
__global__ void k_apply_cbn(const float* __restrict__ gc, const float* __restrict__ bc, int layer) {
    int tid = threadIdx.x;
    int g = tid & 15;
    float mn[4], rsg[4], bb[4];
#pragma unroll
    for (int j = 0; j < 4; j++) {
        int c = 4 * g + j;
        double mean = d_sum1[layer][c] * (1.0 / NN);
        double var  = d_sumsq1[layer][c] * (1.0 / NN) - mean * mean;
        float rs = (float)rsqrt(var + 1e-5);
        mn[j] = (float)mean; rsg[j] = rs * gc[c]; bb[j] = bc[c];
    }
    float4 s = {0,0,0,0}, q = {0,0,0,0};
    int stride = gridDim.x * blockDim.x;
    float4* a4 = (float4*)d_agg;
    const float4* x4 = (const float4*)d_x;
    for (int i = blockIdx.x * blockDim.x + tid; i < NN * 16; i += stride) {
        float4 a = a4[i];
        float4 x = x4[i];
        float4 xn;
        xn.x = (a.x - mn[0]) * rsg[0] + bb[0] + x.x;
        xn.y = (a.y - mn[1]) * rsg[1] + bb[1] + x.y;
        xn.z = (a.z - mn[2]) * rsg[2] + bb[2] + x.z;
        xn.w = (a.w - mn[3]) * rsg[3] + bb[3] + x.w;
        a4[i] = xn;
        s.x += xn.x; s.y += xn.y; s.z += xn.z; s.w += xn.w;
        q.x = fmaf(xn.x, xn.x, q.x); q.y = fmaf(xn.y, xn.y, q.y);
        q.z = fmaf(xn.z, xn.z, q.z); q.w = fmaf(xn.w, xn.w, q.w);
    }
    __shared__ float4 ss[256], sq[256];
    ss[tid] = s; sq[tid] = q;
    __syncthreads();
#pragma unroll
    for (int o = 128; o >= 16; o >>= 1) {
        if (tid < o) {
            ss[tid].x += ss[tid+o].x; ss[tid].y += ss[tid+o].y;
            ss[tid].z += ss[tid+o].z; ss[tid].w += ss[tid+o].w;
            sq[tid].x += sq[tid+o].x; sq[tid].y += sq[tid+o].y;
            sq[tid].z += sq[tid+o].z; sq[tid].w += sq[tid+o].w;
        }
        __syncthreads();
    }
    if (tid < 16) {
        atomicAdd(&d_sum2[layer][4*tid+0], (double)ss[tid].x);
        atomicAdd(&d_sum2[layer][4*tid+1], (double)ss[tid].y);
        atomicAdd(&d_sum2[layer][4*tid+2], (double)ss[tid].z);
        atomicAdd(&d_sum2[layer][4*tid+3], (double)ss[tid].w);
        atomicAdd(&d_sumsq2[layer][4*tid+0], (double)sq[tid].x);
        atomicAdd(&d_sumsq2[layer][4*tid+1], (double)sq[tid].y);
        atomicAdd(&d_sumsq2[layer][4*tid+2], (double)sq[tid].z);
        atomicAdd(&d_sumsq2[layer][4*tid+3], (double)sq[tid].w);
    }
}

// final obn + softplus -> d_x (last layer only)
__global__ void k_final_obn(const float* __restrict__ go, const float* __restrict__ bo, int layer) {
    int tid = threadIdx.x;
    int g = tid & 15;
    float mn[4], rsg[4], bb[4];
#pragma unroll
    for (int j = 0; j < 4; j++) {
        int c = 4 * g + j;
        double mean = d_sum2[layer][c] * (1.0 / NN);
        double var  = d_sumsq2[layer][c] * (1.0 / NN) - mean * mean;
        float rs = (float)rsqrt(var + 1e-5);
        mn[j] = (float)mean; rsg[j] = rs * go[c]; bb[j] = bo[c];
    }
    int stride = gridDim.x * blockDim.x;
    const float4* a4 = (const float4*)d_agg;
    float4* x4 = (float4*)d_x;
    for (int i = blockIdx.x * blockDim.x + tid; i < NN * 16; i += stride) {
        float4 a = a4[i];
        float4 r;
        r.x = softplusf_((a.x - mn[0]) * rsg[0] + bb[0]);
        r.y = softplusf_((a.y - mn[1]) * rsg[1] + bb[1]);
        r.z = softplusf_((a.z - mn[2]) * rsg[2] + bb[2]);
        r.w = softplusf_((a.w - mn[3]) * rsg[3] + bb[3]);
        x4[i] = r;
    }
}

__global__ void k_pool(const int* __restrict__ batch) {
    int i = blockIdx.x * blockDim.x + threadIdx.x;
    if (i < NN * 16) {
        int n = i >> 4, q = i & 15;
        int g = batch[n];
        float4 v = *(const float4*)(d_x + n * HID + 4 * q);
        float* p = d_pool + g * HID + 4 * q;
        asm volatile("red.global.add.v4.f32 [%0], {%1,%2,%3,%4};"
                     :: "l"(p), "f"(v.x), "f"(v.y), "f"(v.z), "f"(v.w) : "memory");
    }
}

__global__ void k_cnt(const int* __restrict__ batch) {
    int n = blockIdx.x * blockDim.x + threadIdx.x;
    if (n < NN) atomicAdd(&d_cnt[batch[n]], 1.0f);
}

__global__ void k_head(const float* __restrict__ W1, const float* __restrict__ b1,
                       const float* __restrict__ W2, const float* __restrict__ b2,
                       float* __restrict__ out)
{
    int g = blockIdx.x;
    int t = threadIdx.x;
    __shared__ float sp[64];
    __shared__ float sh[64];
    float cnt = fmaxf(d_cnt[g], 1.0f);
    sp[t] = d_pool[g * HID + t] / cnt;
    __syncthreads();
    float acc = b1[t];
#pragma unroll
    for (int k = 0; k < 64; k++)
        acc = fmaf(sp[k], W1[k * HID + t], acc);
    float h = acc * sigmoidf_(acc);
    sh[t] = h * W2[t];
    __syncthreads();
    if (t < 32) {
        float v = sh[t] + sh[t + 32];
#pragma unroll
        for (int o = 16; o > 0; o >>= 1)
            v += __shfl_down_sync(0xffffffffu, v, o);
        if (t == 0) out[g] = v + b2[0];
    }
}

// ---------------- launch ----------------
extern "C" void kernel_launch(void* const* d_in, const int* in_sizes, int n_in,
                              void* d_out, int out_size) {
    const int*   z     = (const int*)  d_in[0];
    const int*   ei    = (const int*)  d_in[1];
    const float* ea    = (const float*)d_in[2];
    const int*   batch = (const int*)  d_in[3];
    const float* emb   = (const float*)d_in[4];
    const float* Wf    = (const float*)d_in[5];
    const float* bf    = (const float*)d_in[6];
    const float* Ws    = (const float*)d_in[7];
    const float* bs    = (const float*)d_in[8];
    const float* gc    = (const float*)d_in[9];
    const float* bc    = (const float*)d_in[10];
    const float* go    = (const float*)d_in[11];
    const float* bo    = (const float*)d_in[12];
    const float* W1    = (const float*)d_in[13];
    const float* b1    = (const float*)d_in[14];
    const float* W2    = (const float*)d_in[15];
    const float* b2    = (const float*)d_in[16];
    float* out = (float*)d_out;

    k_gather<<<(NN * HID + 255) / 256, 256>>>(z, emb);
    k_prep_ea<<<(NE * EDIM / 8 + 255) / 256, 256>>>(ea);

    for (int l = 0; l < NLAYERS; l++) {
        const float* Wfl = Wf + l * ZW * HID;
        const float* Wsl = Ws + l * ZW * HID;
        k_node_pre<<<592, 256>>>(Wfl, bf + l * HID, Wsl, bs + l * HID,
                                 go + (l - 1) * HID, bo + (l - 1) * HID, l - 1);
        k_edge_fused<<<888, 128>>>(ei, Wfl, Wsl);
        k_stats_agg<<<256, 256>>>(l);
        k_apply_cbn<<<256, 256>>>(gc + l * HID, bc + l * HID, l);
    }
    k_final_obn<<<256, 256>>>(go + 3 * HID, bo + 3 * HID, 3);

    k_zero_pool<<<(NG * HID + 255) / 256, 256>>>();
    k_pool<<<(NN * 16 + 255) / 256, 256>>>(batch);
    k_cnt<<<(NN + 255) / 256, 256>>>(batch);
    k_head<<<NG, 64>>>(W1, b1, W2, b2, out);
}

// round 16
// speedup vs baseline: 1.0505x; 1.0124x over previous
#include <cuda_runtime.h>
#include <cuda_fp16.h>

#define NN 100000
#define NE 1000000
#define NG 512
#define HID 64
#define EDIM 32
#define ZW 160
#define NLAYERS 4

typedef unsigned long long ull;
typedef unsigned int uint;

// Virtual-channel packing: column v (0..127): even v -> f-channel v/2, odd v -> s-channel v/2.
// d_nd[n*64 + c] = half2(Af_c, As_c); d_ns[n*64 + c] = half2(Bf_c, Bs_c).

// ---------------- scratch ----------------
__device__ float d_x[NN * HID];
__device__ uint  d_nd[NN * 64];
__device__ uint  d_ns[NN * 64];
__device__ float d_agg[NN * HID];
__device__ __half d_ea_h[NE * EDIM];
__device__ double d_sum1[NLAYERS][64];
__device__ double d_sumsq1[NLAYERS][64];
__device__ double d_sum2[NLAYERS][64];
__device__ double d_sumsq2[NLAYERS][64];
__device__ float d_pool[NG * HID];
__device__ float d_cnt[NG];

// ---------------- helpers ----------------
__device__ __forceinline__ float sigmoidf_(float x) {
    return __fdividef(1.0f, 1.0f + __expf(-x));
}
__device__ __forceinline__ float sigmoid_tanh_(float x) {
    float t;
    asm("tanh.approx.f32 %0, %1;" : "=f"(t) : "f"(x * 0.5f));
    return fmaf(0.5f, t, 0.5f);
}
__device__ __forceinline__ float softplusf_(float x) {
    float e = __expf(-fabsf(x));
    return fmaxf(x, 0.0f) + __logf(1.0f + e);
}
__device__ __forceinline__ uint h2u(__half2 h) { return *(uint*)&h; }
__device__ __forceinline__ __half2 u2h(uint u) { return *(__half2*)&u; }
// ex2 on packed halves (one MUFU for two exps)
__device__ __forceinline__ __half2 ex2h2(__half2 x) {
    uint r, xi = h2u(x);
    asm("ex2.approx.f16x2 %0, %1;" : "=r"(r) : "r"(xi));
    return u2h(r);
}

// mma.sync m16n8k16 f16 inputs, f32 accumulate
__device__ __forceinline__ void mma16816(float c[4], const uint a[4], const uint b[2]) {
    asm volatile(
        "mma.sync.aligned.m16n8k16.row.col.f32.f16.f16.f32 "
        "{%0,%1,%2,%3}, {%4,%5,%6,%7}, {%8,%9}, {%0,%1,%2,%3};"
        : "+f"(c[0]), "+f"(c[1]), "+f"(c[2]), "+f"(c[3])
        : "r"(a[0]), "r"(a[1]), "r"(a[2]), "r"(a[3]), "r"(b[0]), "r"(b[1]));
}
__device__ __forceinline__ void ldsm4(uint a[4], const __half* p) {
    uint sa = (uint)__cvta_generic_to_shared(p);
    asm volatile("ldmatrix.sync.aligned.m8n8.x4.shared.b16 {%0,%1,%2,%3}, [%4];"
                 : "=r"(a[0]), "=r"(a[1]), "=r"(a[2]), "=r"(a[3]) : "r"(sa));
}
__device__ __forceinline__ void stsm4(__half* p, uint r0, uint r1, uint r2, uint r3) {
    uint sa = (uint)__cvta_generic_to_shared(p);
    asm volatile("stmatrix.sync.aligned.m8n8.x4.shared.b16 [%0], {%1,%2,%3,%4};"
                 :: "r"(sa), "r"(r0), "r"(r1), "r"(r2), "r"(r3));
}

// ---------------- kernels ----------------

__global__ void k_gather(const int* __restrict__ z, const float* __restrict__ emb) {
    int i = blockIdx.x * blockDim.x + threadIdx.x;
    if (i < NN * HID) {
        int n = i >> 6, c = i & 63;
        d_x[i] = emb[z[n] * HID + c];
        d_agg[i] = 0.f;
    }
    if (i < NLAYERS * 64) {
        int l = i >> 6, c = i & 63;
        d_sum1[l][c] = 0.0; d_sumsq1[l][c] = 0.0;
        d_sum2[l][c] = 0.0; d_sumsq2[l][c] = 0.0;
    }
}

__global__ void k_prep_ea(const float* __restrict__ ea) {
    int i = blockIdx.x * blockDim.x + threadIdx.x;
    if (i < NE * EDIM / 8) {
        const float4* s = (const float4*)ea;
        float4 v0 = __ldcs(s + 2 * i);
        float4 v1 = __ldcs(s + 2 * i + 1);
        uint4 o;
        o.x = h2u(__floats2half2_rn(v0.x, v0.y));
        o.y = h2u(__floats2half2_rn(v0.z, v0.w));
        o.z = h2u(__floats2half2_rn(v1.x, v1.y));
        o.w = h2u(__floats2half2_rn(v1.z, v1.w));
        ((uint4*)d_ea_h)[i] = o;
    }
}

// Tensor-core node pre-GEMM with interleaved virtual channels.
// Warps 0-3 -> d_nd (weight rows 0:64), warps 4-7 -> d_ns (rows 64:128).
__global__ __launch_bounds__(256) void k_node_pre(
    const float* __restrict__ Wf, const float* __restrict__ bf,
    const float* __restrict__ Ws, const float* __restrict__ bs,
    const float* __restrict__ go, const float* __restrict__ bo,
    int prev_layer)
{
    __shared__ __half sxh[64][72];

    int tid = threadIdx.x;
    int warp = tid >> 5;
    int lane = tid & 31;
    int gid = lane >> 2;
    int tig = lane & 3;

    float mn[4], rsg[4], bb[4];
    if (prev_layer >= 0) {
        int q = tid & 15;
#pragma unroll
        for (int j = 0; j < 4; j++) {
            int c = 4 * q + j;
            double mean = d_sum2[prev_layer][c] * (1.0 / NN);
            double var  = d_sumsq2[prev_layer][c] * (1.0 / NN) - mean * mean;
            float rs = (float)rsqrt(var + 1e-5);
            mn[j] = (float)mean; rsg[j] = rs * go[c]; bb[j] = bo[c];
        }
    }

    int rowoff = (warp >= 4) ? 64 : 0;
    uint* outp = (warp >= 4) ? d_ns : d_nd;
    bool has_bias = (warp < 4);
    int vchb = (warp & 3) * 32;

    uint b[4][4][2];
#pragma unroll
    for (int nt = 0; nt < 4; nt++) {
#pragma unroll
        for (int kt = 0; kt < 4; kt++) {
            int v = vchb + nt * 8 + gid;
            const float* Wm = (v & 1) ? Ws : Wf;
            int c = v >> 1;
            int k0 = rowoff + kt * 16 + tig * 2;
            b[nt][kt][0] = h2u(__floats2half2_rn(Wm[k0 * HID + c], Wm[(k0 + 1) * HID + c]));
            b[nt][kt][1] = h2u(__floats2half2_rn(Wm[(k0 + 8) * HID + c], Wm[(k0 + 9) * HID + c]));
        }
    }
    // bias: v0 = vchb+nt*8+tig*2 (even -> bf), v0+1 (odd -> bs)
    float bi[4][2];
#pragma unroll
    for (int nt = 0; nt < 4; nt++) {
        int c = (vchb + nt * 8 + tig * 2) >> 1;
        bi[nt][0] = has_bias ? bf[c] : 0.f;
        bi[nt][1] = has_bias ? bs[c] : 0.f;
    }

    int lrow = lane & 15;
    int lcol = (lane >> 4) * 8;

    for (int nb = blockIdx.x * 64; nb < NN; nb += gridDim.x * 64) {
        int nmax = NN - nb; if (nmax > 64) nmax = 64;

        {
            const float4* x4 = (const float4*)(d_x + (ull)nb * HID);
            float4* a4 = (float4*)(d_agg + (ull)nb * HID);
            float4* xw4 = (float4*)(d_x + (ull)nb * HID);
            for (int i = tid; i < nmax * 16; i += 256) {
                int n = i >> 4, q = i & 15;
                float4 v;
                if (prev_layer >= 0) {
                    float4 a = a4[i];
                    v.x = softplusf_((a.x - mn[0]) * rsg[0] + bb[0]);
                    v.y = softplusf_((a.y - mn[1]) * rsg[1] + bb[1]);
                    v.z = softplusf_((a.z - mn[2]) * rsg[2] + bb[2]);
                    v.w = softplusf_((a.w - mn[3]) * rsg[3] + bb[3]);
                    xw4[i] = v;
                    a4[i] = make_float4(0.f, 0.f, 0.f, 0.f);
                } else {
                    v = x4[i];
                }
                __half2 h0 = __floats2half2_rn(v.x, v.y);
                __half2 h1 = __floats2half2_rn(v.z, v.w);
                *(uint2*)&sxh[n][4 * q] = make_uint2(h2u(h0), h2u(h1));
            }
        }
        __syncthreads();

#pragma unroll
        for (int mt = 0; mt < 4; mt++) {
            float c[4][4];
#pragma unroll
            for (int nt = 0; nt < 4; nt++) {
                c[nt][0] = bi[nt][0]; c[nt][1] = bi[nt][1];
                c[nt][2] = bi[nt][0]; c[nt][3] = bi[nt][1];
            }
#pragma unroll
            for (int kt = 0; kt < 4; kt++) {
                uint a[4];
                ldsm4(a, &sxh[mt * 16 + lrow][kt * 16 + lcol]);
#pragma unroll
                for (int nt = 0; nt < 4; nt++)
                    mma16816(c[nt], a, b[nt][kt]);
            }
            int r0 = nb + mt * 16 + gid;
            int r1 = r0 + 8;
#pragma unroll
            for (int nt = 0; nt < 4; nt++) {
                int u = (vchb >> 1) + nt * 4 + tig;   // uint column = channel
                if (r0 < NN) outp[(ull)r0 * 64 + u] = h2u(__floats2half2_rn(c[nt][0], c[nt][1]));
                if (r1 < NN) outp[(ull)r1 * 64 + u] = h2u(__floats2half2_rn(c[nt][2], c[nt][3]));
            }
        }
        __syncthreads();
    }
}

__global__ void k_zero_pool() {
    int i = blockIdx.x * blockDim.x + threadIdx.x;
    if (i < NG * HID) d_pool[i] = 0.f;
    if (i < NG) d_cnt[i] = 0.f;
}

// Fused edge kernel: interleaved virtual channels; warp w covers vch [w*32, w*32+32).
__global__ __launch_bounds__(128, 6) void k_edge_fused(
    const int* __restrict__ ei,
    const float* __restrict__ Wf, const float* __restrict__ Ws)
{
    __shared__ __half sea_h[32][40];
    __shared__ uint sE[32][68];       // uint col c = half2(Ef_c, Es_c), c in 0..63
    __shared__ int sidx[64];

    int tid = threadIdx.x;
    int warp = tid >> 5;
    int lane = tid & 31;
    int gid = lane >> 2;
    int tig = lane & 3;

    int vchb = warp * 32;

    uint b[4][2][2];
#pragma unroll
    for (int nt = 0; nt < 4; nt++) {
#pragma unroll
        for (int kt = 0; kt < 2; kt++) {
            int v = vchb + nt * 8 + gid;
            const float* Wm = (v & 1) ? Ws : Wf;
            int c = v >> 1;
            int k0 = 128 + kt * 16 + tig * 2;
            b[nt][kt][0] = h2u(__floats2half2_rn(Wm[k0 * HID + c], Wm[(k0 + 1) * HID + c]));
            b[nt][kt][1] = h2u(__floats2half2_rn(Wm[(k0 + 8) * HID + c], Wm[(k0 + 9) * HID + c]));
        }
    }

    int lrow = lane & 15;
    int lcol = (lane >> 4) * 8;
    int srow_off = ((lane >> 3) & 1) * 8 + (lane & 7);
    int scol_off = warp * 16 + ((lane >> 4) << 2);

    const float LOG2E = 1.44269504f;
    const __half2 nlog2e = __floats2half2_rn(-LOG2E, -LOG2E);

    const int stride = gridDim.x * 32;
    int base = blockIdx.x * 32;

    if (base < NE) {
        if (tid < 32)      sidx[tid] = ei[base + tid];
        else if (tid < 64) sidx[tid] = ei[NE + base + tid - 32];
        uint4 t = __ldcs(((const uint4*)(d_ea_h + (ull)base * EDIM)) + tid);
        int e = tid >> 2, seg = tid & 3;
        *(uint4*)&sea_h[e][seg * 8] = t;
    }
    __syncthreads();

    for (; base < NE; base += stride) {
        int nb = base + stride;
        int lb = (nb < NE) ? nb : 0;

        int srcs[8], dsts[8];
#pragma unroll
        for (int t = 0; t < 8; t++) {
            srcs[t] = sidx[warp * 8 + t];
            dsts[t] = sidx[32 + warp * 8 + t];
        }

        uint4 nv = __ldcs(((const uint4*)(d_ea_h + (ull)lb * EDIM)) + tid);
        int nidx = 0;
        if (tid < 32)      nidx = ei[lb + tid];
        else if (tid < 64) nidx = ei[NE + lb + tid - 32];

        // ---- GEMM: sequential m-tiles, ldmatrix A, stmatrix C ----
#pragma unroll
        for (int mt = 0; mt < 2; mt++) {
            float c[4][4];
#pragma unroll
            for (int nt = 0; nt < 4; nt++)
#pragma unroll
                for (int j = 0; j < 4; j++) c[nt][j] = 0.f;
#pragma unroll
            for (int kt = 0; kt < 2; kt++) {
                uint a[4];
                ldsm4(a, &sea_h[mt * 16 + lrow][kt * 16 + lcol]);
#pragma unroll
                for (int nt = 0; nt < 4; nt++)
                    mma16816(c[nt], a, b[nt][kt]);
            }
            __half* p0 = (__half*)&sE[mt * 16 + srow_off][scol_off];
            stsm4(p0,
                  h2u(__floats2half2_rn(c[0][0], c[0][1])),
                  h2u(__floats2half2_rn(c[0][2], c[0][3])),
                  h2u(__floats2half2_rn(c[1][0], c[1][1])),
                  h2u(__floats2half2_rn(c[1][2], c[1][3])));
            stsm4(p0 + 16,
                  h2u(__floats2half2_rn(c[2][0], c[2][1])),
                  h2u(__floats2half2_rn(c[2][2], c[2][3])),
                  h2u(__floats2half2_rn(c[3][0], c[3][1])),
                  h2u(__floats2half2_rn(c[3][2], c[3][3])));
        }
        __syncthreads();

        {
            int e = tid >> 2, seg = tid & 3;
            *(uint4*)&sea_h[e][seg * 8] = nv;
            if (tid < 64) sidx[tid] = nidx;
        }

        // ---- apply: half2 = (pf_c, ps_c); shared ex2.f16x2 for softplus ----
#pragma unroll
        for (int g2 = 0; g2 < 2; g2++) {
            uint2 nd[4], ns[4];
#pragma unroll
            for (int t = 0; t < 4; t++) {
                int idx = g2 * 4 + t;
                nd[t] = __ldg((const uint2*)&d_nd[(ull)dsts[idx] * 64 + 2 * lane]);
                ns[t] = __ldg((const uint2*)&d_ns[(ull)srcs[idx] * 64 + 2 * lane]);
            }
#pragma unroll
            for (int t = 0; t < 4; t++) {
                int idx = g2 * 4 + t;
                int e = warp * 8 + idx;

                uint2 se = *(uint2*)&sE[e][2 * lane];
                __half2 h0 = __hadd2(__hadd2(u2h(se.x), u2h(nd[t].x)), u2h(ns[t].x)); // (pf0, ps0)
                __half2 h1 = __hadd2(__hadd2(u2h(se.y), u2h(nd[t].y)), u2h(ns[t].y)); // (pf1, ps1)

                float2 v0 = __half22float2(h0);
                float2 v1 = __half22float2(h1);

                // shared exp for softplus: pack (ps0, ps1), e = 2^{-|ps|*log2e}
                __half2 pp = __highs2half2(h0, h1);
                __half2 q = __hmul2(__habs2(pp), nlog2e);
                __half2 E = ex2h2(q);
                float e0 = __low2float(E), e1 = __high2float(E);

                float sp0 = fmaxf(v0.y, 0.f) + __logf(1.0f + e0);
                float sp1 = fmaxf(v1.y, 0.f) + __logf(1.0f + e1);

                float m0 = sigmoid_tanh_(v0.x) * sp0;
                float m1 = sigmoid_tanh_(v1.x) * sp1;

                float* dp = d_agg + (ull)dsts[idx] * HID + 2 * lane;
                asm volatile("red.global.add.v2.f32 [%0], {%1,%2};"
                             :: "l"(dp), "f"(m0), "f"(m1) : "memory");
            }
        }
        __syncthreads();
    }
}

// float4-vectorized channel stats of d_agg -> d_sum1[layer]
__global__ void k_stats_agg(int layer) {
    int tid = threadIdx.x;
    float4 s = {0,0,0,0}, q = {0,0,0,0};
    int stride = gridDim.x * blockDim.x;
    const float4* a4 = (const float4*)d_agg;
    for (int i = blockIdx.x * blockDim.x + tid; i < NN * 16; i += stride) {
        float4 v = a4[i];
        s.x += v.x; s.y += v.y; s.z += v.z; s.w += v.w;
        q.x = fmaf(v.x, v.x, q.x); q.y = fmaf(v.y, v.y, q.y);
        q.z = fmaf(v.z, v.z, q.z); q.w = fmaf(v.w, v.w, q.w);
    }
    __shared__ float4 ss[256], sq[256];
    ss[tid] = s; sq[tid] = q;
    __syncthreads();
#pragma unroll
    for (int o = 128; o >= 16; o >>= 1) {
        if (tid < o) {
            ss[tid].x += ss[tid+o].x; ss[tid].y += ss[tid+o].y;
            ss[tid].z += ss[tid+o].z; ss[tid].w += ss[tid+o].w;
            sq[tid].x += sq[tid+o].x; sq[tid].y += sq[tid+o].y;
            sq[tid].z += sq[tid+o].z; sq[tid].w += sq[tid+o].w;
        }
        __syncthreads();
    }
    if (tid < 16) {
        atomicAdd(&d_sum1[layer][4*tid+0], (double)ss[tid].x);
        atomicAdd(&d_sum1[layer][4*tid+1], (double)ss[tid].y);
        atomicAdd(&d_sum1[layer][4*tid+2], (double)ss[tid].z);
        atomicAdd(&d_sum1[layer][4*tid+3], (double)ss[tid].w);
        atomicAdd(&d_sumsq1[layer][4*tid+0], (double)sq[tid].x);
        atomicAdd(&d_sumsq1[layer][4*tid+1], (double)sq[tid].y);
        atomicAdd(&d_sumsq1[layer][4*tid+2], (double)sq[tid].z);
        atomicAdd(&d_sumsq1[layer][4*tid+3], (double)sq[tid].w);
    }
}

// apply cbn + residual (float4), write x_new into d_agg, accumulate obn stats
__global__ void k_apply_cbn(const float* __restrict__ gc, const float* __restrict__ bc, int layer) {
    int tid = threadIdx.x;
    int g = tid & 15;
    float mn[4], rsg[4], bb[4];
#pragma unroll
    for (int j = 0; j < 4; j++) {
        int c = 4 * g + j;
        double mean = d_sum1[layer][c] * (1.0 / NN);
        double var  = d_sumsq1[layer][c] * (1.0 / NN) - mean * mean;
        float rs = (float)rsqrt(var + 1e-5);
        mn[j] = (float)mean; rsg[j] = rs * gc[c]; bb[j] = bc[c];
    }
    float4 s = {0,0,0,0}, q = {0,0,0,0};
    int stride = gridDim.x * blockDim.x;
    float4* a4 = (float4*)d_agg;
    const float4* x4 = (const float4*)d_x;
    for (int i = blockIdx.x * blockDim.x + tid; i < NN * 16; i += stride) {
        float4 a = a4[i];
        float4 x = x4[i];
        float4 xn;
        xn.x = (a.x - mn[0]) * rsg[0] + bb[0] + x.x;
        xn.y = (a.y - mn[1]) * rsg[1] + bb[1] + x.y;
        xn.z = (a.z - mn[2]) * rsg[2] + bb[2] + x.z;
        xn.w = (a.w - mn[3]) * rsg[3] + bb[3] + x.w;
        a4[i] = xn;
        s.x += xn.x; s.y += xn.y; s.z += xn.z; s.w += xn.w;
        q.x = fmaf(xn.x, xn.x, q.x); q.y = fmaf(xn.y, xn.y, q.y);
        q.z = fmaf(xn.z, xn.z, q.z); q.w = fmaf(xn.w, xn.w, q.w);
    }
    __shared__ float4 ss[256], sq[256];
    ss[tid] = s; sq[tid] = q;
    __syncthreads();
#pragma unroll
    for (int o = 128; o >= 16; o >>= 1) {
        if (tid < o) {
            ss[tid].x += ss[tid+o].x; ss[tid].y += ss[tid+o].y;
            ss[tid].z += ss[tid+o].z; ss[tid].w += ss[tid+o].w;
            sq[tid].x += sq[tid+o].x; sq[tid].y += sq[tid+o].y;
            sq[tid].z += sq[tid+o].z; sq[tid].w += sq[tid+o].w;
        }
        __syncthreads();
    }
    if (tid < 16) {
        atomicAdd(&d_sum2[layer][4*tid+0], (double)ss[tid].x);
        atomicAdd(&d_sum2[layer][4*tid+1], (double)ss[tid].y);
        atomicAdd(&d_sum2[layer][4*tid+2], (double)ss[tid].z);
        atomicAdd(&d_sum2[layer][4*tid+3], (double)ss[tid].w);
        atomicAdd(&d_sumsq2[layer][4*tid+0], (double)sq[tid].x);
        atomicAdd(&d_sumsq2[layer][4*tid+1], (double)sq[tid].y);
        atomicAdd(&d_sumsq2[layer][4*tid+2], (double)sq[tid].z);
        atomicAdd(&d_sumsq2[layer][4*tid+3], (double)sq[tid].w);
    }
}

// final obn + softplus -> d_x (last layer only)
__global__ void k_final_obn(const float* __restrict__ go, const float* __restrict__ bo, int layer) {
    int tid = threadIdx.x;
    int g = tid & 15;
    float mn[4], rsg[4], bb[4];
#pragma unroll
    for (int j = 0; j < 4; j++) {
        int c = 4 * g + j;
        double mean = d_sum2[layer][c] * (1.0 / NN);
        double var  = d_sumsq2[layer][c] * (1.0 / NN) - mean * mean;
        float rs = (float)rsqrt(var + 1e-5);
        mn[j] = (float)mean; rsg[j] = rs * go[c]; bb[j] = bo[c];
    }
    int stride = gridDim.x * blockDim.x;
    const float4* a4 = (const float4*)d_agg;
    float4* x4 = (float4*)d_x;
    for (int i = blockIdx.x * blockDim.x + tid; i < NN * 16; i += stride) {
        float4 a = a4[i];
        float4 r;
        r.x = softplusf_((a.x - mn[0]) * rsg[0] + bb[0]);
        r.y = softplusf_((a.y - mn[1]) * rsg[1] + bb[1]);
        r.z = softplusf_((a.z - mn[2]) * rsg[2] + bb[2]);
        r.w = softplusf_((a.w - mn[3]) * rsg[3] + bb[3]);
        x4[i] = r;
    }
}

__global__ void k_pool(const int* __restrict__ batch) {
    int i = blockIdx.x * blockDim.x + threadIdx.x;
    if (i < NN * 16) {
        int n = i >> 4, q = i & 15;
        int g = batch[n];
        float4 v = *(const float4*)(d_x + n * HID + 4 * q);
        float* p = d_pool + g * HID + 4 * q;
        asm volatile("red.global.add.v4.f32 [%0], {%1,%2,%3,%4};"
                     :: "l"(p), "f"(v.x), "f"(v.y), "f"(v.z), "f"(v.w) : "memory");
    }
}

__global__ void k_cnt(const int* __restrict__ batch) {
    int n = blockIdx.x * blockDim.x + threadIdx.x;
    if (n < NN) atomicAdd(&d_cnt[batch[n]], 1.0f);
}

__global__ void k_head(const float* __restrict__ W1, const float* __restrict__ b1,
                       const float* __restrict__ W2, const float* __restrict__ b2,
                       float* __restrict__ out)
{
    int g = blockIdx.x;
    int t = threadIdx.x;
    __shared__ float sp[64];
    __shared__ float sh[64];
    float cnt = fmaxf(d_cnt[g], 1.0f);
    sp[t] = d_pool[g * HID + t] / cnt;
    __syncthreads();
    float acc = b1[t];
#pragma unroll
    for (int k = 0; k < 64; k++)
        acc = fmaf(sp[k], W1[k * HID + t], acc);
    float h = acc * sigmoidf_(acc);
    sh[t] = h * W2[t];
    __syncthreads();
    if (t < 32) {
        float v = sh[t] + sh[t + 32];
#pragma unroll
        for (int o = 16; o > 0; o >>= 1)
            v += __shfl_down_sync(0xffffffffu, v, o);
        if (t == 0) out[g] = v + b2[0];
    }
}

// ---------------- launch ----------------
extern "C" void kernel_launch(void* const* d_in, const int* in_sizes, int n_in,
                              void* d_out, int out_size) {
    const int*   z     = (const int*)  d_in[0];
    const int*   ei    = (const int*)  d_in[1];
    const float* ea    = (const float*)d_in[2];
    const int*   batch = (const int*)  d_in[3];
    const float* emb   = (const float*)d_in[4];
    const float* Wf    = (const float*)d_in[5];
    const float* bf    = (const float*)d_in[6];
    const float* Ws    = (const float*)d_in[7];
    const float* bs    = (const float*)d_in[8];
    const float* gc    = (const float*)d_in[9];
    const float* bc    = (const float*)d_in[10];
    const float* go    = (const float*)d_in[11];
    const float* bo    = (const float*)d_in[12];
    const float* W1    = (const float*)d_in[13];
    const float* b1    = (const float*)d_in[14];
    const float* W2    = (const float*)d_in[15];
    const float* b2    = (const float*)d_in[16];
    float* out = (float*)d_out;

    k_gather<<<(NN * HID + 255) / 256, 256>>>(z, emb);
    k_prep_ea<<<(NE * EDIM / 8 + 255) / 256, 256>>>(ea);

    for (int l = 0; l < NLAYERS; l++) {
        const float* Wfl = Wf + l * ZW * HID;
        const float* Wsl = Ws + l * ZW * HID;
        k_node_pre<<<592, 256>>>(Wfl, bf + l * HID, Wsl, bs + l * HID,
                                 go + (l - 1) * HID, bo + (l - 1) * HID, l - 1);
        k_edge_fused<<<888, 128>>>(ei, Wfl, Wsl);
        k_stats_agg<<<256, 256>>>(l);
        k_apply_cbn<<<256, 256>>>(gc + l * HID, bc + l * HID, l);
    }
    k_final_obn<<<256, 256>>>(go + 3 * HID, bo + 3 * HID, 3);

    k_zero_pool<<<(NG * HID + 255) / 256, 256>>>();
    k_pool<<<(NN * 16 + 255) / 256, 256>>>(batch);
    k_cnt<<<(NN + 255) / 256, 256>>>(batch);
    k_head<<<NG, 64>>>(W1, b1, W2, b2, out);
}

// round 17
// speedup vs baseline: 1.0571x; 1.0062x over previous
#include <cuda_runtime.h>
#include <cuda_fp16.h>

#define NN 100000
#define NE 1000000
#define NG 512
#define HID 64
#define EDIM 32
#define ZW 160
#define NLAYERS 4

typedef unsigned long long ull;
typedef unsigned int uint;

// Virtual-channel packing: column v (0..127): even v -> f-channel v/2, odd v -> s-channel v/2.
// d_nd[n*64 + c] = half2(Af_c, As_c); d_ns[n*64 + c] = half2(Bf_c, Bs_c).

// ---------------- scratch ----------------
__device__ __half d_xh[NN * HID];     // node features (fp16)
__device__ uint  d_nd[NN * 64];
__device__ uint  d_ns[NN * 64];
__device__ float d_agg[NN * HID];
__device__ __half d_ea_h[NE * EDIM];
__device__ double d_sum1[NLAYERS][64];
__device__ double d_sumsq1[NLAYERS][64];
__device__ double d_sum2[NLAYERS][64];
__device__ double d_sumsq2[NLAYERS][64];
__device__ float d_pool[NG * HID];
__device__ float d_cnt[NG];
__device__ uint d_barc[NLAYERS];      // grid-barrier arrive counters
__device__ volatile uint d_barrel[NLAYERS];  // grid-barrier release flags

// ---------------- helpers ----------------
__device__ __forceinline__ float sigmoidf_(float x) {
    return __fdividef(1.0f, 1.0f + __expf(-x));
}
__device__ __forceinline__ float sigmoid_tanh_(float x) {
    float t;
    asm("tanh.approx.f32 %0, %1;" : "=f"(t) : "f"(x * 0.5f));
    return fmaf(0.5f, t, 0.5f);
}
__device__ __forceinline__ float softplusf_(float x) {
    float e = __expf(-fabsf(x));
    return fmaxf(x, 0.0f) + __logf(1.0f + e);
}
__device__ __forceinline__ uint h2u(__half2 h) { return *(uint*)&h; }
__device__ __forceinline__ __half2 u2h(uint u) { return *(__half2*)&u; }
__device__ __forceinline__ __half2 ex2h2(__half2 x) {
    uint r, xi = h2u(x);
    asm("ex2.approx.f16x2 %0, %1;" : "=r"(r) : "r"(xi));
    return u2h(r);
}

__device__ __forceinline__ void mma16816(float c[4], const uint a[4], const uint b[2]) {
    asm volatile(
        "mma.sync.aligned.m16n8k16.row.col.f32.f16.f16.f32 "
        "{%0,%1,%2,%3}, {%4,%5,%6,%7}, {%8,%9}, {%0,%1,%2,%3};"
        : "+f"(c[0]), "+f"(c[1]), "+f"(c[2]), "+f"(c[3])
        : "r"(a[0]), "r"(a[1]), "r"(a[2]), "r"(a[3]), "r"(b[0]), "r"(b[1]));
}
__device__ __forceinline__ void ldsm4(uint a[4], const __half* p) {
    uint sa = (uint)__cvta_generic_to_shared(p);
    asm volatile("ldmatrix.sync.aligned.m8n8.x4.shared.b16 {%0,%1,%2,%3}, [%4];"
                 : "=r"(a[0]), "=r"(a[1]), "=r"(a[2]), "=r"(a[3]) : "r"(sa));
}
__device__ __forceinline__ void stsm4(__half* p, uint r0, uint r1, uint r2, uint r3) {
    uint sa = (uint)__cvta_generic_to_shared(p);
    asm volatile("stmatrix.sync.aligned.m8n8.x4.shared.b16 [%0], {%1,%2,%3,%4};"
                 :: "r"(sa), "r"(r0), "r"(r1), "r"(r2), "r"(r3));
}

// ---------------- kernels ----------------

__global__ void k_gather(const int* __restrict__ z, const float* __restrict__ emb) {
    int i = blockIdx.x * blockDim.x + threadIdx.x;
    if (i < NN * HID) {
        int n = i >> 6, c = i & 63;
        d_xh[i] = __float2half(emb[z[n] * HID + c]);
        d_agg[i] = 0.f;
    }
    if (i < NLAYERS * 64) {
        int l = i >> 6, c = i & 63;
        d_sum1[l][c] = 0.0; d_sumsq1[l][c] = 0.0;
        d_sum2[l][c] = 0.0; d_sumsq2[l][c] = 0.0;
    }
    if (i < NLAYERS) { d_barc[i] = 0u; d_barrel[i] = 0u; }
}

__global__ void k_prep_ea(const float* __restrict__ ea) {
    int i = blockIdx.x * blockDim.x + threadIdx.x;
    if (i < NE * EDIM / 8) {
        const float4* s = (const float4*)ea;
        float4 v0 = __ldcs(s + 2 * i);
        float4 v1 = __ldcs(s + 2 * i + 1);
        uint4 o;
        o.x = h2u(__floats2half2_rn(v0.x, v0.y));
        o.y = h2u(__floats2half2_rn(v0.z, v0.w));
        o.z = h2u(__floats2half2_rn(v1.x, v1.y));
        o.w = h2u(__floats2half2_rn(v1.z, v1.w));
        ((uint4*)d_ea_h)[i] = o;
    }
}

// Tensor-core node pre-GEMM with interleaved virtual channels, fp16 x.
__global__ __launch_bounds__(256) void k_node_pre(
    const float* __restrict__ Wf, const float* __restrict__ bf,
    const float* __restrict__ Ws, const float* __restrict__ bs,
    const float* __restrict__ go, const float* __restrict__ bo,
    int prev_layer)
{
    __shared__ __half sxh[64][72];

    int tid = threadIdx.x;
    int warp = tid >> 5;
    int lane = tid & 31;
    int gid = lane >> 2;
    int tig = lane & 3;

    float mn[4], rsg[4], bb[4];
    if (prev_layer >= 0) {
        int q = tid & 15;
#pragma unroll
        for (int j = 0; j < 4; j++) {
            int c = 4 * q + j;
            double mean = d_sum2[prev_layer][c] * (1.0 / NN);
            double var  = d_sumsq2[prev_layer][c] * (1.0 / NN) - mean * mean;
            float rs = (float)rsqrt(var + 1e-5);
            mn[j] = (float)mean; rsg[j] = rs * go[c]; bb[j] = bo[c];
        }
    }

    int rowoff = (warp >= 4) ? 64 : 0;
    uint* outp = (warp >= 4) ? d_ns : d_nd;
    bool has_bias = (warp < 4);
    int vchb = (warp & 3) * 32;

    uint b[4][4][2];
#pragma unroll
    for (int nt = 0; nt < 4; nt++) {
#pragma unroll
        for (int kt = 0; kt < 4; kt++) {
            int v = vchb + nt * 8 + gid;
            const float* Wm = (v & 1) ? Ws : Wf;
            int c = v >> 1;
            int k0 = rowoff + kt * 16 + tig * 2;
            b[nt][kt][0] = h2u(__floats2half2_rn(Wm[k0 * HID + c], Wm[(k0 + 1) * HID + c]));
            b[nt][kt][1] = h2u(__floats2half2_rn(Wm[(k0 + 8) * HID + c], Wm[(k0 + 9) * HID + c]));
        }
    }
    float bi[4][2];
#pragma unroll
    for (int nt = 0; nt < 4; nt++) {
        int c = (vchb + nt * 8 + tig * 2) >> 1;
        bi[nt][0] = has_bias ? bf[c] : 0.f;
        bi[nt][1] = has_bias ? bs[c] : 0.f;
    }

    int lrow = lane & 15;
    int lcol = (lane >> 4) * 8;

    for (int nb = blockIdx.x * 64; nb < NN; nb += gridDim.x * 64) {
        int nmax = NN - nb; if (nmax > 64) nmax = 64;

        {
            float4* a4 = (float4*)(d_agg + (ull)nb * HID);
            for (int i = tid; i < nmax * 16; i += 256) {
                int n = i >> 4, q = i & 15;
                uint2 hx;
                if (prev_layer >= 0) {
                    float4 a = a4[i];
                    float vx = softplusf_((a.x - mn[0]) * rsg[0] + bb[0]);
                    float vy = softplusf_((a.y - mn[1]) * rsg[1] + bb[1]);
                    float vz = softplusf_((a.z - mn[2]) * rsg[2] + bb[2]);
                    float vw = softplusf_((a.w - mn[3]) * rsg[3] + bb[3]);
                    hx.x = h2u(__floats2half2_rn(vx, vy));
                    hx.y = h2u(__floats2half2_rn(vz, vw));
                    *(uint2*)&d_xh[(ull)nb * HID + 4 * i] = hx;
                    a4[i] = make_float4(0.f, 0.f, 0.f, 0.f);
                } else {
                    hx = *(const uint2*)&d_xh[(ull)nb * HID + 4 * i];
                }
                *(uint2*)&sxh[n][4 * q] = hx;
            }
        }
        __syncthreads();

#pragma unroll
        for (int mt = 0; mt < 4; mt++) {
            float c[4][4];
#pragma unroll
            for (int nt = 0; nt < 4; nt++) {
                c[nt][0] = bi[nt][0]; c[nt][1] = bi[nt][1];
                c[nt][2] = bi[nt][0]; c[nt][3] = bi[nt][1];
            }
#pragma unroll
            for (int kt = 0; kt < 4; kt++) {
                uint a[4];
                ldsm4(a, &sxh[mt * 16 + lrow][kt * 16 + lcol]);
#pragma unroll
                for (int nt = 0; nt < 4; nt++)
                    mma16816(c[nt], a, b[nt][kt]);
            }
            int r0 = nb + mt * 16 + gid;
            int r1 = r0 + 8;
#pragma unroll
            for (int nt = 0; nt < 4; nt++) {
                int u = (vchb >> 1) + nt * 4 + tig;
                if (r0 < NN) outp[(ull)r0 * 64 + u] = h2u(__floats2half2_rn(c[nt][0], c[nt][1]));
                if (r1 < NN) outp[(ull)r1 * 64 + u] = h2u(__floats2half2_rn(c[nt][2], c[nt][3]));
            }
        }
        __syncthreads();
    }
}

__global__ void k_zero_pool() {
    int i = blockIdx.x * blockDim.x + threadIdx.x;
    if (i < NG * HID) d_pool[i] = 0.f;
    if (i < NG) d_cnt[i] = 0.f;
}

// Fused edge kernel (round-16 version, unchanged).
__global__ __launch_bounds__(128, 6) void k_edge_fused(
    const int* __restrict__ ei,
    const float* __restrict__ Wf, const float* __restrict__ Ws)
{
    __shared__ __half sea_h[32][40];
    __shared__ uint sE[32][68];
    __shared__ int sidx[64];

    int tid = threadIdx.x;
    int warp = tid >> 5;
    int lane = tid & 31;
    int gid = lane >> 2;
    int tig = lane & 3;

    int vchb = warp * 32;

    uint b[4][2][2];
#pragma unroll
    for (int nt = 0; nt < 4; nt++) {
#pragma unroll
        for (int kt = 0; kt < 2; kt++) {
            int v = vchb + nt * 8 + gid;
            const float* Wm = (v & 1) ? Ws : Wf;
            int c = v >> 1;
            int k0 = 128 + kt * 16 + tig * 2;
            b[nt][kt][0] = h2u(__floats2half2_rn(Wm[k0 * HID + c], Wm[(k0 + 1) * HID + c]));
            b[nt][kt][1] = h2u(__floats2half2_rn(Wm[(k0 + 8) * HID + c], Wm[(k0 + 9) * HID + c]));
        }
    }

    int lrow = lane & 15;
    int lcol = (lane >> 4) * 8;
    int srow_off = ((lane >> 3) & 1) * 8 + (lane & 7);
    int scol_off = warp * 16 + ((lane >> 4) << 2);

    const float LOG2E = 1.44269504f;
    const __half2 nlog2e = __floats2half2_rn(-LOG2E, -LOG2E);

    const int stride = gridDim.x * 32;
    int base = blockIdx.x * 32;

    if (base < NE) {
        if (tid < 32)      sidx[tid] = ei[base + tid];
        else if (tid < 64) sidx[tid] = ei[NE + base + tid - 32];
        uint4 t = __ldcs(((const uint4*)(d_ea_h + (ull)base * EDIM)) + tid);
        int e = tid >> 2, seg = tid & 3;
        *(uint4*)&sea_h[e][seg * 8] = t;
    }
    __syncthreads();

    for (; base < NE; base += stride) {
        int nb = base + stride;
        int lb = (nb < NE) ? nb : 0;

        int srcs[8], dsts[8];
#pragma unroll
        for (int t = 0; t < 8; t++) {
            srcs[t] = sidx[warp * 8 + t];
            dsts[t] = sidx[32 + warp * 8 + t];
        }

        uint4 nv = __ldcs(((const uint4*)(d_ea_h + (ull)lb * EDIM)) + tid);
        int nidx = 0;
        if (tid < 32)      nidx = ei[lb + tid];
        else if (tid < 64) nidx = ei[NE + lb + tid - 32];

#pragma unroll
        for (int mt = 0; mt < 2; mt++) {
            float c[4][4];
#pragma unroll
            for (int nt = 0; nt < 4; nt++)
#pragma unroll
                for (int j = 0; j < 4; j++) c[nt][j] = 0.f;
#pragma unroll
            for (int kt = 0; kt < 2; kt++) {
                uint a[4];
                ldsm4(a, &sea_h[mt * 16 + lrow][kt * 16 + lcol]);
#pragma unroll
                for (int nt = 0; nt < 4; nt++)
                    mma16816(c[nt], a, b[nt][kt]);
            }
            __half* p0 = (__half*)&sE[mt * 16 + srow_off][scol_off];
            stsm4(p0,
                  h2u(__floats2half2_rn(c[0][0], c[0][1])),
                  h2u(__floats2half2_rn(c[0][2], c[0][3])),
                  h2u(__floats2half2_rn(c[1][0], c[1][1])),
                  h2u(__floats2half2_rn(c[1][2], c[1][3])));
            stsm4(p0 + 16,
                  h2u(__floats2half2_rn(c[2][0], c[2][1])),
                  h2u(__floats2half2_rn(c[2][2], c[2][3])),
                  h2u(__floats2half2_rn(c[3][0], c[3][1])),
                  h2u(__floats2half2_rn(c[3][2], c[3][3])));
        }
        __syncthreads();

        {
            int e = tid >> 2, seg = tid & 3;
            *(uint4*)&sea_h[e][seg * 8] = nv;
            if (tid < 64) sidx[tid] = nidx;
        }

#pragma unroll
        for (int g2 = 0; g2 < 2; g2++) {
            uint2 nd[4], ns[4];
#pragma unroll
            for (int t = 0; t < 4; t++) {
                int idx = g2 * 4 + t;
                nd[t] = __ldg((const uint2*)&d_nd[(ull)dsts[idx] * 64 + 2 * lane]);
                ns[t] = __ldg((const uint2*)&d_ns[(ull)srcs[idx] * 64 + 2 * lane]);
            }
#pragma unroll
            for (int t = 0; t < 4; t++) {
                int idx = g2 * 4 + t;
                int e = warp * 8 + idx;

                uint2 se = *(uint2*)&sE[e][2 * lane];
                __half2 h0 = __hadd2(__hadd2(u2h(se.x), u2h(nd[t].x)), u2h(ns[t].x));
                __half2 h1 = __hadd2(__hadd2(u2h(se.y), u2h(nd[t].y)), u2h(ns[t].y));

                float2 v0 = __half22float2(h0);
                float2 v1 = __half22float2(h1);

                __half2 pp = __highs2half2(h0, h1);
                __half2 q = __hmul2(__habs2(pp), nlog2e);
                __half2 E = ex2h2(q);
                float e0 = __low2float(E), e1 = __high2float(E);

                float sp0 = fmaxf(v0.y, 0.f) + __logf(1.0f + e0);
                float sp1 = fmaxf(v1.y, 0.f) + __logf(1.0f + e1);

                float m0 = sigmoid_tanh_(v0.x) * sp0;
                float m1 = sigmoid_tanh_(v1.x) * sp1;

                float* dp = d_agg + (ull)dsts[idx] * HID + 2 * lane;
                asm volatile("red.global.add.v2.f32 [%0], {%1,%2};"
                             :: "l"(dp), "f"(m0), "f"(m1) : "memory");
            }
        }
        __syncthreads();
    }
}

// Fused BN: phase1 stats of d_agg -> d_sum1; grid barrier; phase2 cbn apply
// + residual (fp16 x) + obn stats -> d_sum2. 256 blocks (co-resident).
__global__ __launch_bounds__(256) void k_bn(
    const float* __restrict__ gc, const float* __restrict__ bc, int layer)
{
    int tid = threadIdx.x;
    int g = tid & 15;
    int stride = gridDim.x * blockDim.x;
    __shared__ float4 ss[256], sq[256];

    // ---- phase 1: stats of d_agg ----
    {
        float4 s = {0,0,0,0}, q = {0,0,0,0};
        const float4* a4 = (const float4*)d_agg;
        for (int i = blockIdx.x * blockDim.x + tid; i < NN * 16; i += stride) {
            float4 v = a4[i];
            s.x += v.x; s.y += v.y; s.z += v.z; s.w += v.w;
            q.x = fmaf(v.x, v.x, q.x); q.y = fmaf(v.y, v.y, q.y);
            q.z = fmaf(v.z, v.z, q.z); q.w = fmaf(v.w, v.w, q.w);
        }
        ss[tid] = s; sq[tid] = q;
        __syncthreads();
#pragma unroll
        for (int o = 128; o >= 16; o >>= 1) {
            if (tid < o) {
                ss[tid].x += ss[tid+o].x; ss[tid].y += ss[tid+o].y;
                ss[tid].z += ss[tid+o].z; ss[tid].w += ss[tid+o].w;
                sq[tid].x += sq[tid+o].x; sq[tid].y += sq[tid+o].y;
                sq[tid].z += sq[tid+o].z; sq[tid].w += sq[tid+o].w;
            }
            __syncthreads();
        }
        if (tid < 16) {
            atomicAdd(&d_sum1[layer][4*tid+0], (double)ss[tid].x);
            atomicAdd(&d_sum1[layer][4*tid+1], (double)ss[tid].y);
            atomicAdd(&d_sum1[layer][4*tid+2], (double)ss[tid].z);
            atomicAdd(&d_sum1[layer][4*tid+3], (double)ss[tid].w);
            atomicAdd(&d_sumsq1[layer][4*tid+0], (double)sq[tid].x);
            atomicAdd(&d_sumsq1[layer][4*tid+1], (double)sq[tid].y);
            atomicAdd(&d_sumsq1[layer][4*tid+2], (double)sq[tid].z);
            atomicAdd(&d_sumsq1[layer][4*tid+3], (double)sq[tid].w);
        }
    }
    __threadfence();
    __syncthreads();

    // ---- grid barrier ----
    if (tid == 0) {
        uint t = atomicAdd(&d_barc[layer], 1u);
        if (t == gridDim.x - 1) {
            d_barrel[layer] = 1u;
        } else {
            while (d_barrel[layer] == 0u) { }
        }
    }
    __syncthreads();
    __threadfence();

    // ---- phase 2: cbn apply + residual + obn stats ----
    float mn[4], rsg[4], bb[4];
#pragma unroll
    for (int j = 0; j < 4; j++) {
        int c = 4 * g + j;
        double mean = d_sum1[layer][c] * (1.0 / NN);
        double var  = d_sumsq1[layer][c] * (1.0 / NN) - mean * mean;
        float rs = (float)rsqrt(var + 1e-5);
        mn[j] = (float)mean; rsg[j] = rs * gc[c]; bb[j] = bc[c];
    }
    {
        float4 s = {0,0,0,0}, q = {0,0,0,0};
        float4* a4 = (float4*)d_agg;
        for (int i = blockIdx.x * blockDim.x + tid; i < NN * 16; i += stride) {
            float4 a = a4[i];
            uint2 hx = *(const uint2*)&d_xh[4 * (ull)i];
            float2 x01 = __half22float2(u2h(hx.x));
            float2 x23 = __half22float2(u2h(hx.y));
            float4 xn;
            xn.x = (a.x - mn[0]) * rsg[0] + bb[0] + x01.x;
            xn.y = (a.y - mn[1]) * rsg[1] + bb[1] + x01.y;
            xn.z = (a.z - mn[2]) * rsg[2] + bb[2] + x23.x;
            xn.w = (a.w - mn[3]) * rsg[3] + bb[3] + x23.y;
            a4[i] = xn;
            s.x += xn.x; s.y += xn.y; s.z += xn.z; s.w += xn.w;
            q.x = fmaf(xn.x, xn.x, q.x); q.y = fmaf(xn.y, xn.y, q.y);
            q.z = fmaf(xn.z, xn.z, q.z); q.w = fmaf(xn.w, xn.w, q.w);
        }
        __syncthreads();
        ss[tid] = s; sq[tid] = q;
        __syncthreads();
#pragma unroll
        for (int o = 128; o >= 16; o >>= 1) {
            if (tid < o) {
                ss[tid].x += ss[tid+o].x; ss[tid].y += ss[tid+o].y;
                ss[tid].z += ss[tid+o].z; ss[tid].w += ss[tid+o].w;
                sq[tid].x += sq[tid+o].x; sq[tid].y += sq[tid+o].y;
                sq[tid].z += sq[tid+o].z; sq[tid].w += sq[tid+o].w;
            }
            __syncthreads();
        }
        if (tid < 16) {
            atomicAdd(&d_sum2[layer][4*tid+0], (double)ss[tid].x);
            atomicAdd(&d_sum2[layer][4*tid+1], (double)ss[tid].y);
            atomicAdd(&d_sum2[layer][4*tid+2], (double)ss[tid].z);
            atomicAdd(&d_sum2[layer][4*tid+3], (double)ss[tid].w);
            atomicAdd(&d_sumsq2[layer][4*tid+0], (double)sq[tid].x);
            atomicAdd(&d_sumsq2[layer][4*tid+1], (double)sq[tid].y);
            atomicAdd(&d_sumsq2[layer][4*tid+2], (double)sq[tid].z);
            atomicAdd(&d_sumsq2[layer][4*tid+3], (double)sq[tid].w);
        }
    }
}

// final obn + softplus -> d_xh (fp16)
__global__ void k_final_obn(const float* __restrict__ go, const float* __restrict__ bo, int layer) {
    int tid = threadIdx.x;
    int g = tid & 15;
    float mn[4], rsg[4], bb[4];
#pragma unroll
    for (int j = 0; j < 4; j++) {
        int c = 4 * g + j;
        double mean = d_sum2[layer][c] * (1.0 / NN);
        double var  = d_sumsq2[layer][c] * (1.0 / NN) - mean * mean;
        float rs = (float)rsqrt(var + 1e-5);
        mn[j] = (float)mean; rsg[j] = rs * go[c]; bb[j] = bo[c];
    }
    int stride = gridDim.x * blockDim.x;
    const float4* a4 = (const float4*)d_agg;
    for (int i = blockIdx.x * blockDim.x + tid; i < NN * 16; i += stride) {
        float4 a = a4[i];
        float rx = softplusf_((a.x - mn[0]) * rsg[0] + bb[0]);
        float ry = softplusf_((a.y - mn[1]) * rsg[1] + bb[1]);
        float rz = softplusf_((a.z - mn[2]) * rsg[2] + bb[2]);
        float rw = softplusf_((a.w - mn[3]) * rsg[3] + bb[3]);
        uint2 o;
        o.x = h2u(__floats2half2_rn(rx, ry));
        o.y = h2u(__floats2half2_rn(rz, rw));
        *(uint2*)&d_xh[4 * (ull)i] = o;
    }
}

__global__ void k_pool(const int* __restrict__ batch) {
    int i = blockIdx.x * blockDim.x + threadIdx.x;
    if (i < NN * 16) {
        int n = i >> 4, q = i & 15;
        int g = batch[n];
        uint2 hv = *(const uint2*)&d_xh[(ull)n * HID + 4 * q];
        float2 v01 = __half22float2(u2h(hv.x));
        float2 v23 = __half22float2(u2h(hv.y));
        float* p = d_pool + g * HID + 4 * q;
        asm volatile("red.global.add.v4.f32 [%0], {%1,%2,%3,%4};"
                     :: "l"(p), "f"(v01.x), "f"(v01.y), "f"(v23.x), "f"(v23.y) : "memory");
    }
}

__global__ void k_cnt(const int* __restrict__ batch) {
    int n = blockIdx.x * blockDim.x + threadIdx.x;
    if (n < NN) atomicAdd(&d_cnt[batch[n]], 1.0f);
}

__global__ void k_head(const float* __restrict__ W1, const float* __restrict__ b1,
                       const float* __restrict__ W2, const float* __restrict__ b2,
                       float* __restrict__ out)
{
    int g = blockIdx.x;
    int t = threadIdx.x;
    __shared__ float sp[64];
    __shared__ float sh[64];
    float cnt = fmaxf(d_cnt[g], 1.0f);
    sp[t] = d_pool[g * HID + t] / cnt;
    __syncthreads();
    float acc = b1[t];
#pragma unroll
    for (int k = 0; k < 64; k++)
        acc = fmaf(sp[k], W1[k * HID + t], acc);
    float h = acc * sigmoidf_(acc);
    sh[t] = h * W2[t];
    __syncthreads();
    if (t < 32) {
        float v = sh[t] + sh[t + 32];
#pragma unroll
        for (int o = 16; o > 0; o >>= 1)
            v += __shfl_down_sync(0xffffffffu, v, o);
        if (t == 0) out[g] = v + b2[0];
    }
}

// ---------------- launch ----------------
extern "C" void kernel_launch(void* const* d_in, const int* in_sizes, int n_in,
                              void* d_out, int out_size) {
    const int*   z     = (const int*)  d_in[0];
    const int*   ei    = (const int*)  d_in[1];
    const float* ea    = (const float*)d_in[2];
    const int*   batch = (const int*)  d_in[3];
    const float* emb   = (const float*)d_in[4];
    const float* Wf    = (const float*)d_in[5];
    const float* bf    = (const float*)d_in[6];
    const float* Ws    = (const float*)d_in[7];
    const float* bs    = (const float*)d_in[8];
    const float* gc    = (const float*)d_in[9];
    const float* bc    = (const float*)d_in[10];
    const float* go    = (const float*)d_in[11];
    const float* bo    = (const float*)d_in[12];
    const float* W1    = (const float*)d_in[13];
    const float* b1    = (const float*)d_in[14];
    const float* W2    = (const float*)d_in[15];
    const float* b2    = (const float*)d_in[16];
    float* out = (float*)d_out;

    k_gather<<<(NN * HID + 255) / 256, 256>>>(z, emb);
    k_prep_ea<<<(NE * EDIM / 8 + 255) / 256, 256>>>(ea);

    for (int l = 0; l < NLAYERS; l++) {
        const float* Wfl = Wf + l * ZW * HID;
        const float* Wsl = Ws + l * ZW * HID;
        k_node_pre<<<592, 256>>>(Wfl, bf + l * HID, Wsl, bs + l * HID,
                                 go + (l - 1) * HID, bo + (l - 1) * HID, l - 1);
        k_edge_fused<<<888, 128>>>(ei, Wfl, Wsl);
        k_bn<<<256, 256>>>(gc + l * HID, bc + l * HID, l);
    }
    k_final_obn<<<256, 256>>>(go + 3 * HID, bo + 3 * HID, 3);

    k_zero_pool<<<(NG * HID + 255) / 256, 256>>>();
    k_pool<<<(NN * 16 + 255) / 256, 256>>>(batch);
    k_cnt<<<(NN + 255) / 256, 256>>>(batch);
    k_head<<<NG, 64>>>(W1, b1, W2, b2, out);
}